// round 3
// baseline (speedup 1.0000x reference)
#include <cuda_runtime.h>
#include <cstdint>
#include <math.h>

#define NN 100000
#define EE 3200000
#define NB 98  // ceil(NN/1024)

// ---------------- device scratch (static, no runtime alloc) ----------------
__device__ int   g_is64;
__device__ int   g_deg[NN];
__device__ float g_dis[NN];
__device__ int   g_off[NN + 1];
__device__ int   g_cur[NN];
__device__ int   g_bsum[NB];
__device__ int   g_src32[EE];
__device__ int   g_dst32[EE];
__device__ int   g_srcs[EE];                       // CSR-sorted src per dst
__device__ float g_xagg[(size_t)NN * 256];         // aggregated [latent|condition]
__device__ float g_act [(size_t)NN * 512];         // tanh(conv1|conv2) activations
__device__ float g_h2  [(size_t)NN * 128];         // g_act @ W_o

// ---------------- dtype detection: int64 vs int32 edge_index ----------------
// If int64 (LE), high 32-bit word of every value (< 100000) is 0. Sample 2048
// odd words; all-zero => int64. For int32 data these are node ids; P(all 0)~0.
__global__ void detect_kernel(const unsigned int* __restrict__ w) {
    __shared__ int ok;
    if (threadIdx.x == 0) ok = 1;
    __syncthreads();
    for (int k = threadIdx.x; k < 2048; k += blockDim.x) {
        if (w[2 * k + 1] != 0u) ok = 0;
    }
    __syncthreads();
    if (threadIdx.x == 0) g_is64 = ok;
}

__global__ void convert_kernel(const void* __restrict__ ei) {
    int e = blockIdx.x * blockDim.x + threadIdx.x;
    if (e >= EE) return;
    if (g_is64) {
        const long long* p = (const long long*)ei;
        g_src32[e] = (int)p[e];
        g_dst32[e] = (int)p[EE + e];
    } else {
        const int* p = (const int*)ei;
        g_src32[e] = p[e];
        g_dst32[e] = p[EE + e];
    }
}

// ---------------- degree / norm / CSR build ----------------
__global__ void init_deg_kernel() {
    int i = blockIdx.x * blockDim.x + threadIdx.x;
    if (i < NN) g_deg[i] = 1;  // self loop pre-counted
}

__global__ void count_deg_kernel() {
    int e = blockIdx.x * blockDim.x + threadIdx.x;
    if (e < EE) atomicAdd(&g_deg[g_dst32[e]], 1);
}

__global__ void scan1_kernel() {
    __shared__ int sh[1024];
    int i = blockIdx.x * 1024 + threadIdx.x;
    int v = 0;
    if (i < NN) {
        int d = g_deg[i];
        g_dis[i] = rsqrtf((float)d);
        v = d - 1;  // non-self in-degree
    }
    sh[threadIdx.x] = v;
    __syncthreads();
    for (int ofs = 1; ofs < 1024; ofs <<= 1) {
        int t = 0;
        if ((int)threadIdx.x >= ofs) t = sh[threadIdx.x - ofs];
        __syncthreads();
        sh[threadIdx.x] += t;
        __syncthreads();
    }
    int incl = sh[threadIdx.x];
    if (i < NN) g_off[i] = incl - v;  // exclusive
    if (threadIdx.x == 1023) g_bsum[blockIdx.x] = incl;
}

__global__ void scan2_kernel() {
    int run = 0;
    for (int b = 0; b < NB; b++) {
        int t = g_bsum[b];
        g_bsum[b] = run;
        run += t;
    }
}

__global__ void scan3_kernel() {
    int i = blockIdx.x * 1024 + threadIdx.x;
    if (i < NN) {
        int o = g_off[i] + g_bsum[blockIdx.x];
        g_off[i] = o;
        g_cur[i] = o;
    }
    if (i == 0) g_off[NN] = EE;
}

__global__ void scatter_kernel() {
    int e = blockIdx.x * blockDim.x + threadIdx.x;
    if (e < EE) {
        int d = g_dst32[e];
        int p = atomicAdd(&g_cur[d], 1);
        g_srcs[p] = g_src32[e];
    }
}

// ---------------- aggregation 1: raw features (256 wide) ----------------
// xagg[d] = dd * ( sum_{e: dst=d} dis[src]*x[src]  +  dd*x[d] ),  x = [latent|condition]
__global__ void __launch_bounds__(64) aggx_kernel(const float* __restrict__ lat,
                                                  const float* __restrict__ cond) {
    int node = blockIdx.x;
    int t = threadIdx.x;  // 0..63
    __shared__ int   s_s[64];
    __shared__ float s_w[64];
    float dd = g_dis[node];
    const float4* base = (t < 32) ? (const float4*)lat : (const float4*)cond;
    int l4 = t & 31;
    float4 v0 = base[(size_t)node * 32 + l4];
    float4 acc = make_float4(dd * v0.x, dd * v0.y, dd * v0.z, dd * v0.w);
    int beg = g_off[node], end = g_off[node + 1];
    for (int c0 = beg; c0 < end; c0 += 64) {
        int m = end - c0;
        if (m > 64) m = 64;
        __syncthreads();
        if (t < m) {
            int s = g_srcs[c0 + t];
            s_s[t] = s;
            s_w[t] = g_dis[s];
        }
        __syncthreads();
        #pragma unroll 4
        for (int j = 0; j < m; ++j) {
            float w = s_w[j];
            float4 v = base[(size_t)s_s[j] * 32 + l4];
            acc.x += w * v.x;
            acc.y += w * v.y;
            acc.z += w * v.z;
            acc.w += w * v.w;
        }
    }
    acc.x *= dd; acc.y *= dd; acc.z *= dd; acc.w *= dd;
    ((float4*)g_xagg)[(size_t)node * 64 + t] = acc;
}

// ---------------- SIMT fp32 GEMM: 64x64 tile, 4x4 microtile, 256 threads ----
__device__ __forceinline__ void gemm_body(const float* __restrict__ A, int lda,
                                          const float* __restrict__ B, int ldb,
                                          const float* __restrict__ bias,
                                          float* __restrict__ C, int ldc,
                                          int K, bool dotanh) {
    __shared__ float As[16][68];
    __shared__ float Bs[16][68];
    int tid = threadIdx.x;
    int tx = tid & 15, ty = tid >> 4;
    int row0 = blockIdx.y * 64;
    int col0 = blockIdx.x * 64;
    float acc[4][4] = {};
    for (int k0 = 0; k0 < K; k0 += 16) {
        {
            int r = tid >> 2;
            int c = (tid & 3) << 2;
            float4 v = make_float4(0.f, 0.f, 0.f, 0.f);
            int gr = row0 + r;
            if (gr < NN) v = *(const float4*)(A + (size_t)gr * lda + (k0 + c));
            As[c + 0][r] = v.x;
            As[c + 1][r] = v.y;
            As[c + 2][r] = v.z;
            As[c + 3][r] = v.w;
        }
        {
            int r = tid >> 4;
            int c = (tid & 15) << 2;
            float4 v = *(const float4*)(B + (size_t)(k0 + r) * ldb + (col0 + c));
            Bs[r][c + 0] = v.x;
            Bs[r][c + 1] = v.y;
            Bs[r][c + 2] = v.z;
            Bs[r][c + 3] = v.w;
        }
        __syncthreads();
        #pragma unroll
        for (int kk = 0; kk < 16; ++kk) {
            float a[4], b[4];
            #pragma unroll
            for (int i = 0; i < 4; i++) a[i] = As[kk][(ty << 2) + i];
            #pragma unroll
            for (int j = 0; j < 4; j++) b[j] = Bs[kk][(tx << 2) + j];
            #pragma unroll
            for (int i = 0; i < 4; i++)
                #pragma unroll
                for (int j = 0; j < 4; j++)
                    acc[i][j] = fmaf(a[i], b[j], acc[i][j]);
        }
        __syncthreads();
    }
    #pragma unroll
    for (int i = 0; i < 4; i++) {
        int gr = row0 + (ty << 2) + i;
        if (gr < NN) {
            #pragma unroll
            for (int j = 0; j < 4; j++) {
                int gc = col0 + (tx << 2) + j;
                float v = acc[i][j];
                if (bias) v += bias[gc];
                if (dotanh) v = tanhf(v);
                C[(size_t)gr * ldc + gc] = v;
            }
        }
    }
}

__global__ void __launch_bounds__(256) gemm_z_kernel(const float* __restrict__ W,
                                                     const float* __restrict__ b) {
    gemm_body(g_xagg, 256, W, 256, b, g_act, 512, 128, true);
}
__global__ void __launch_bounds__(256) gemm_c_kernel(const float* __restrict__ W,
                                                     const float* __restrict__ b) {
    gemm_body(g_xagg + 128, 256, W, 256, b, g_act + 256, 512, 128, true);
}
__global__ void __launch_bounds__(256) gemm_o_kernel(const float* __restrict__ W) {
    gemm_body(g_act, 512, W, 128, nullptr, g_h2, 128, 512, false);
}

// ---------------- aggregation 2: h2 (128 wide), one warp per node ----------
__global__ void __launch_bounds__(256) agg2_kernel(const float* __restrict__ bo,
                                                   float* __restrict__ out) {
    int gw = (int)((blockIdx.x * blockDim.x + threadIdx.x) >> 5);
    int lane = threadIdx.x & 31;
    if (gw >= NN) return;
    const float4* H = (const float4*)g_h2;
    float dd = g_dis[gw];
    float4 v0 = H[(size_t)gw * 32 + lane];
    float4 acc = make_float4(dd * v0.x, dd * v0.y, dd * v0.z, dd * v0.w);
    int beg = g_off[gw], end = g_off[gw + 1];
    #pragma unroll 4
    for (int j = beg; j < end; ++j) {
        int s = g_srcs[j];
        float w = g_dis[s];
        float4 v = H[(size_t)s * 32 + lane];
        acc.x += w * v.x;
        acc.y += w * v.y;
        acc.z += w * v.z;
        acc.w += w * v.w;
    }
    float4 b = ((const float4*)bo)[lane];
    float4 r = make_float4(dd * acc.x + b.x, dd * acc.y + b.y,
                           dd * acc.z + b.z, dd * acc.w + b.w);
    ((float4*)out)[(size_t)gw * 32 + lane] = r;
}

// ---------------- launch ----------------
extern "C" void kernel_launch(void* const* d_in, const int* in_sizes, int n_in,
                              void* d_out, int out_size) {
    const float* latent    = (const float*)d_in[0];
    const float* condition = (const float*)d_in[1];
    const void*  ei        = d_in[2];
    const float* Wz = (const float*)d_in[3];
    const float* bz = (const float*)d_in[4];
    const float* Wc = (const float*)d_in[5];
    const float* bc = (const float*)d_in[6];
    const float* Wo = (const float*)d_in[7];
    const float* bo = (const float*)d_in[8];
    float* out = (float*)d_out;

    detect_kernel<<<1, 256>>>((const unsigned int*)ei);
    convert_kernel<<<(EE + 255) / 256, 256>>>(ei);
    init_deg_kernel<<<(NN + 255) / 256, 256>>>();
    count_deg_kernel<<<(EE + 255) / 256, 256>>>();
    scan1_kernel<<<NB, 1024>>>();
    scan2_kernel<<<1, 1>>>();
    scan3_kernel<<<NB, 1024>>>();
    scatter_kernel<<<(EE + 255) / 256, 256>>>();
    aggx_kernel<<<NN, 64>>>(latent, condition);
    gemm_z_kernel<<<dim3(4, (NN + 63) / 64), 256>>>(Wz, bz);
    gemm_c_kernel<<<dim3(4, (NN + 63) / 64), 256>>>(Wc, bc);
    gemm_o_kernel<<<dim3(2, (NN + 63) / 64), 256>>>(Wo);
    agg2_kernel<<<(NN * 32 + 255) / 256, 256>>>(bo, out);
}

// round 5
// speedup vs baseline: 1.6046x; 1.6046x over previous
#include <cuda_runtime.h>
#include <cuda_bf16.h>
#include <cstdint>
#include <math.h>

#define NN 100000
#define EE 3200000
#define NB 98  // ceil(NN/1024)

// ---------------- device scratch (static, no runtime alloc) ----------------
__device__ int   g_is64;
__device__ int   g_deg[NN];
__device__ float g_dis[NN];
__device__ int   g_off[NN + 1];
__device__ int   g_cur[NN];
__device__ int   g_bsum[NB];
__device__ int   g_src32[EE];
__device__ int   g_dst32[EE];
__device__ int   g_srcs[EE];                       // CSR-sorted src per dst
__device__ float g_xagg[(size_t)NN * 256];         // aggregated [latent|condition]
__device__ float g_act [(size_t)NN * 512];         // tanh(conv1|conv2) activations
__device__ float g_h2  [(size_t)NN * 128];         // g_act @ W_o

// ==================== warp-MMA helpers (sm_80+ HMMA path) ====================
__device__ __forceinline__ uint32_t smem_u32(const void* p) {
    uint32_t a;
    asm("{ .reg .u64 t; cvta.to.shared.u64 t, %1; cvt.u32.u64 %0, t; }" : "=r"(a) : "l"(p));
    return a;
}

__device__ __forceinline__ void mma16816(float* d, const uint32_t* a, const uint32_t* b) {
    asm volatile(
        "mma.sync.aligned.m16n8k16.row.col.f32.bf16.bf16.f32 "
        "{%0,%1,%2,%3}, {%4,%5,%6,%7}, {%8,%9}, {%0,%1,%2,%3};"
        : "+f"(d[0]), "+f"(d[1]), "+f"(d[2]), "+f"(d[3])
        : "r"(a[0]), "r"(a[1]), "r"(a[2]), "r"(a[3]), "r"(b[0]), "r"(b[1]));
}

__device__ __forceinline__ void ldmx4(uint32_t* r, uint32_t addr) {
    asm volatile("ldmatrix.sync.aligned.m8n8.x4.shared.b16 {%0,%1,%2,%3}, [%4];"
                 : "=r"(r[0]), "=r"(r[1]), "=r"(r[2]), "=r"(r[3]) : "r"(addr));
}
__device__ __forceinline__ void ldmx4t(uint32_t* r, uint32_t addr) {
    asm volatile("ldmatrix.sync.aligned.m8n8.x4.trans.shared.b16 {%0,%1,%2,%3}, [%4];"
                 : "=r"(r[0]), "=r"(r[1]), "=r"(r[2]), "=r"(r[3]) : "r"(addr));
}

// pack fp32x4 -> (hi bf16x4, lo bf16x4)
__device__ __forceinline__ void split4(float4 v, uint2& uh, uint2& ul) {
    __nv_bfloat16 h0 = __float2bfloat16(v.x);
    __nv_bfloat16 h1 = __float2bfloat16(v.y);
    __nv_bfloat16 h2 = __float2bfloat16(v.z);
    __nv_bfloat16 h3 = __float2bfloat16(v.w);
    __nv_bfloat16 l0 = __float2bfloat16(v.x - __bfloat162float(h0));
    __nv_bfloat16 l1 = __float2bfloat16(v.y - __bfloat162float(h1));
    __nv_bfloat16 l2 = __float2bfloat16(v.z - __bfloat162float(h2));
    __nv_bfloat16 l3 = __float2bfloat16(v.w - __bfloat162float(h3));
    uh.x = ((uint32_t)__bfloat16_as_ushort(h1) << 16) | __bfloat16_as_ushort(h0);
    uh.y = ((uint32_t)__bfloat16_as_ushort(h3) << 16) | __bfloat16_as_ushort(h2);
    ul.x = ((uint32_t)__bfloat16_as_ushort(l1) << 16) | __bfloat16_as_ushort(l0);
    ul.y = ((uint32_t)__bfloat16_as_ushort(l3) << 16) | __bfloat16_as_ushort(l2);
}

// ==================== bf16x3 GEMM: C[128-tile, 128-chunk] = op(A @ W + bias) ====================
// Block tile 128x128, 8 warps of 32x64, K-chunks of 32.
// A: [NN, LDA] fp32 row-major. W: [KTOT, ldw] fp32 row-major (read at ncol0). C fp32.
template <int KTOT, int LDA, int LDC, bool TANH, bool HASB>
__device__ __forceinline__ void gemm_mma(const float* __restrict__ A,
                                         const float* __restrict__ W, int ldw,
                                         const float* __restrict__ bias,
                                         float* __restrict__ C,
                                         int row0, int ncol0) {
    __shared__ __align__(16) uint16_t sAh[128 * 40], sAl[128 * 40];  // stride 40 halves (80B)
    __shared__ __align__(16) uint16_t sBh[32 * 136], sBl[32 * 136];  // stride 136 halves (272B)

    int tid = threadIdx.x, lane = tid & 31, wid = tid >> 5;
    int wm = wid & 3, wn = wid >> 2;  // warp tile: rows [wm*32,+32), cols [wn*64,+64)

    float acc[2][8][4];
    #pragma unroll
    for (int i = 0; i < 2; i++)
        #pragma unroll
        for (int j = 0; j < 8; j++)
            #pragma unroll
            for (int k = 0; k < 4; k++) acc[i][j][k] = 0.f;

    uint32_t aAh = smem_u32(sAh), aAl = smem_u32(sAl);
    uint32_t aBh = smem_u32(sBh), aBl = smem_u32(sBl);
    // ldmatrix address bases (per-thread invariants)
    uint32_t offA0 = (uint32_t)(((wm * 32 + (lane & 15)) * 40 + ((lane >> 4) << 3)) * 2);
    uint32_t offB0 = (uint32_t)(((lane & 15) * 136 + wn * 64 + ((lane >> 4) << 3)) * 2);

    for (int k0 = 0; k0 < KTOT; k0 += 32) {
        // ---- stage A chunk [128 x 32] fp32 -> hi/lo bf16
        #pragma unroll
        for (int i = 0; i < 4; i++) {
            int lin = tid + 256 * i;
            int r = lin >> 3, c4 = lin & 7;
            int gr = row0 + r;
            float4 v = make_float4(0.f, 0.f, 0.f, 0.f);
            if (gr < NN) v = *(const float4*)(A + (size_t)gr * LDA + k0 + c4 * 4);
            uint2 uh, ul;
            split4(v, uh, ul);
            *(uint2*)((char*)sAh + (r * 40 + c4 * 4) * 2) = uh;
            *(uint2*)((char*)sAl + (r * 40 + c4 * 4) * 2) = ul;
        }
        // ---- stage B chunk [32 x 128] from W
        #pragma unroll
        for (int i = 0; i < 4; i++) {
            int lin = tid + 256 * i;
            int kr = lin >> 5, c4 = lin & 31;
            float4 v = *(const float4*)(W + (size_t)(k0 + kr) * ldw + ncol0 + c4 * 4);
            uint2 uh, ul;
            split4(v, uh, ul);
            *(uint2*)((char*)sBh + (kr * 136 + c4 * 4) * 2) = uh;
            *(uint2*)((char*)sBl + (kr * 136 + c4 * 4) * 2) = ul;
        }
        __syncthreads();
        #pragma unroll
        for (int kb = 0; kb < 32; kb += 16) {
            uint32_t ah[2][4], al[2][4], bb[4][4];
            #pragma unroll
            for (int mi = 0; mi < 2; mi++) {
                uint32_t off = offA0 + (uint32_t)((mi * 16 * 40 + kb) * 2);
                ldmx4(ah[mi], aAh + off);
                ldmx4(al[mi], aAl + off);
            }
            #pragma unroll
            for (int g = 0; g < 4; g++)
                ldmx4t(bb[g], aBh + offB0 + (uint32_t)((kb * 136 + g * 16) * 2));
            #pragma unroll
            for (int mi = 0; mi < 2; mi++)
                #pragma unroll
                for (int g = 0; g < 4; g++) {
                    mma16816(acc[mi][2 * g],     ah[mi], &bb[g][0]);
                    mma16816(acc[mi][2 * g + 1], ah[mi], &bb[g][2]);
                    mma16816(acc[mi][2 * g],     al[mi], &bb[g][0]);
                    mma16816(acc[mi][2 * g + 1], al[mi], &bb[g][2]);
                }
            #pragma unroll
            for (int g = 0; g < 4; g++)
                ldmx4t(bb[g], aBl + offB0 + (uint32_t)((kb * 136 + g * 16) * 2));
            #pragma unroll
            for (int mi = 0; mi < 2; mi++)
                #pragma unroll
                for (int g = 0; g < 4; g++) {
                    mma16816(acc[mi][2 * g],     ah[mi], &bb[g][0]);
                    mma16816(acc[mi][2 * g + 1], ah[mi], &bb[g][2]);
                }
        }
        __syncthreads();
    }

    // ---- epilogue: direct fp32 stores (float2 per d-pair)
    int rbase = row0 + wm * 32 + (lane >> 2);
    #pragma unroll
    for (int mi = 0; mi < 2; mi++)
        #pragma unroll
        for (int ni = 0; ni < 8; ni++) {
            int cl = wn * 64 + ni * 8 + (lane & 3) * 2;
            float b0 = 0.f, b1 = 0.f;
            if (HASB) { b0 = bias[cl]; b1 = bias[cl + 1]; }
            #pragma unroll
            for (int h = 0; h < 2; h++) {
                int gr = rbase + mi * 16 + h * 8;
                if (gr < NN) {
                    float v0 = acc[mi][ni][2 * h] + b0;
                    float v1 = acc[mi][ni][2 * h + 1] + b1;
                    if (TANH) { v0 = tanhf(v0); v1 = tanhf(v1); }
                    *(float2*)(C + (size_t)gr * LDC + cl) = make_float2(v0, v1);
                }
            }
        }
}

__global__ void __launch_bounds__(256, 2) gemm_zc_mma(const float* __restrict__ Wz,
                                                      const float* __restrict__ bz,
                                                      const float* __restrict__ Wc,
                                                      const float* __restrict__ bc) {
    int conv = blockIdx.z;
    int nb = blockIdx.y * 128;
    const float* W = conv ? Wc : Wz;
    const float* b = conv ? bc : bz;
    gemm_mma<128, 256, 512, true, true>(g_xagg + conv * 128, W, 256, b + nb,
                                        g_act + conv * 256 + nb, blockIdx.x * 128, nb);
}

__global__ void __launch_bounds__(256, 2) gemm_o_mma(const float* __restrict__ Wo) {
    gemm_mma<512, 512, 128, false, false>(g_act, Wo, 128, nullptr,
                                          g_h2, blockIdx.x * 128, 0);
}

// ---------------- dtype detection: int64 vs int32 edge_index ----------------
__global__ void detect_kernel(const unsigned int* __restrict__ w) {
    __shared__ int ok;
    if (threadIdx.x == 0) ok = 1;
    __syncthreads();
    for (int k = threadIdx.x; k < 2048; k += blockDim.x) {
        if (w[2 * k + 1] != 0u) ok = 0;
    }
    __syncthreads();
    if (threadIdx.x == 0) g_is64 = ok;
}

__global__ void convert_kernel(const void* __restrict__ ei) {
    int e = blockIdx.x * blockDim.x + threadIdx.x;
    if (e >= EE) return;
    if (g_is64) {
        const long long* p = (const long long*)ei;
        g_src32[e] = (int)p[e];
        g_dst32[e] = (int)p[EE + e];
    } else {
        const int* p = (const int*)ei;
        g_src32[e] = p[e];
        g_dst32[e] = p[EE + e];
    }
}

// ---------------- degree / norm / CSR build ----------------
__global__ void init_deg_kernel() {
    int i = blockIdx.x * blockDim.x + threadIdx.x;
    if (i < NN) g_deg[i] = 1;
}

__global__ void count_deg_kernel() {
    int e = blockIdx.x * blockDim.x + threadIdx.x;
    if (e < EE) atomicAdd(&g_deg[g_dst32[e]], 1);
}

__global__ void scan1_kernel() {
    __shared__ int sh[1024];
    int i = blockIdx.x * 1024 + threadIdx.x;
    int v = 0;
    if (i < NN) {
        int d = g_deg[i];
        g_dis[i] = rsqrtf((float)d);
        v = d - 1;
    }
    sh[threadIdx.x] = v;
    __syncthreads();
    for (int ofs = 1; ofs < 1024; ofs <<= 1) {
        int t = 0;
        if ((int)threadIdx.x >= ofs) t = sh[threadIdx.x - ofs];
        __syncthreads();
        sh[threadIdx.x] += t;
        __syncthreads();
    }
    int incl = sh[threadIdx.x];
    if (i < NN) g_off[i] = incl - v;
    if (threadIdx.x == 1023) g_bsum[blockIdx.x] = incl;
}

__global__ void scan2_kernel() {
    int run = 0;
    for (int b = 0; b < NB; b++) {
        int t = g_bsum[b];
        g_bsum[b] = run;
        run += t;
    }
}

__global__ void scan3_kernel() {
    int i = blockIdx.x * 1024 + threadIdx.x;
    if (i < NN) {
        int o = g_off[i] + g_bsum[blockIdx.x];
        g_off[i] = o;
        g_cur[i] = o;
    }
    if (i == 0) g_off[NN] = EE;
}

__global__ void scatter_kernel() {
    int e = blockIdx.x * blockDim.x + threadIdx.x;
    if (e < EE) {
        int d = g_dst32[e];
        int p = atomicAdd(&g_cur[d], 1);
        g_srcs[p] = g_src32[e];
    }
}

// ---------------- aggregation 1: raw features (256 wide) ----------------
__global__ void __launch_bounds__(64) aggx_kernel(const float* __restrict__ lat,
                                                  const float* __restrict__ cond) {
    int node = blockIdx.x;
    int t = threadIdx.x;
    __shared__ int   s_s[64];
    __shared__ float s_w[64];
    float dd = g_dis[node];
    const float4* base = (t < 32) ? (const float4*)lat : (const float4*)cond;
    int l4 = t & 31;
    float4 v0 = base[(size_t)node * 32 + l4];
    float4 acc = make_float4(dd * v0.x, dd * v0.y, dd * v0.z, dd * v0.w);
    int beg = g_off[node], end = g_off[node + 1];
    for (int c0 = beg; c0 < end; c0 += 64) {
        int m = end - c0;
        if (m > 64) m = 64;
        __syncthreads();
        if (t < m) {
            int s = g_srcs[c0 + t];
            s_s[t] = s;
            s_w[t] = g_dis[s];
        }
        __syncthreads();
        #pragma unroll 4
        for (int j = 0; j < m; ++j) {
            float w = s_w[j];
            float4 v = base[(size_t)s_s[j] * 32 + l4];
            acc.x += w * v.x;
            acc.y += w * v.y;
            acc.z += w * v.z;
            acc.w += w * v.w;
        }
    }
    acc.x *= dd; acc.y *= dd; acc.z *= dd; acc.w *= dd;
    ((float4*)g_xagg)[(size_t)node * 64 + t] = acc;
}

// ---------------- aggregation 2: h2 (128 wide), one warp per node ----------
__global__ void __launch_bounds__(256) agg2_kernel(const float* __restrict__ bo,
                                                   float* __restrict__ out) {
    int gw = (int)((blockIdx.x * blockDim.x + threadIdx.x) >> 5);
    int lane = threadIdx.x & 31;
    if (gw >= NN) return;
    const float4* H = (const float4*)g_h2;
    float dd = g_dis[gw];
    float4 v0 = H[(size_t)gw * 32 + lane];
    float4 acc = make_float4(dd * v0.x, dd * v0.y, dd * v0.z, dd * v0.w);
    int beg = g_off[gw], end = g_off[gw + 1];
    #pragma unroll 4
    for (int j = beg; j < end; ++j) {
        int s = g_srcs[j];
        float w = g_dis[s];
        float4 v = H[(size_t)s * 32 + lane];
        acc.x += w * v.x;
        acc.y += w * v.y;
        acc.z += w * v.z;
        acc.w += w * v.w;
    }
    float4 b = ((const float4*)bo)[lane];
    float4 r = make_float4(dd * acc.x + b.x, dd * acc.y + b.y,
                           dd * acc.z + b.z, dd * acc.w + b.w);
    ((float4*)out)[(size_t)gw * 32 + lane] = r;
}

// ---------------- launch ----------------
extern "C" void kernel_launch(void* const* d_in, const int* in_sizes, int n_in,
                              void* d_out, int out_size) {
    const float* latent    = (const float*)d_in[0];
    const float* condition = (const float*)d_in[1];
    const void*  ei        = d_in[2];
    const float* Wz = (const float*)d_in[3];
    const float* bz = (const float*)d_in[4];
    const float* Wc = (const float*)d_in[5];
    const float* bc = (const float*)d_in[6];
    const float* Wo = (const float*)d_in[7];
    const float* bo = (const float*)d_in[8];
    float* out = (float*)d_out;

    detect_kernel<<<1, 256>>>((const unsigned int*)ei);
    convert_kernel<<<(EE + 255) / 256, 256>>>(ei);
    init_deg_kernel<<<(NN + 255) / 256, 256>>>();
    count_deg_kernel<<<(EE + 255) / 256, 256>>>();
    scan1_kernel<<<NB, 1024>>>();
    scan2_kernel<<<1, 1>>>();
    scan3_kernel<<<NB, 1024>>>();
    scatter_kernel<<<(EE + 255) / 256, 256>>>();
    aggx_kernel<<<NN, 64>>>(latent, condition);

    int ntiles = (NN + 127) / 128;  // 782
    gemm_zc_mma<<<dim3(ntiles, 2, 2), 256>>>(Wz, bz, Wc, bc);
    gemm_o_mma<<<dim3(ntiles, 1, 1), 256>>>(Wo);

    agg2_kernel<<<(NN * 32 + 255) / 256, 256>>>(bo, out);
}

// round 6
// speedup vs baseline: 1.8451x; 1.1499x over previous
#include <cuda_runtime.h>
#include <cuda_bf16.h>
#include <cuda_fp16.h>
#include <cstdint>
#include <math.h>

#define NN 100000
#define EE 3200000
#define NB 98  // ceil(NN/1024)

// ---------------- device scratch (static, no runtime alloc) ----------------
__device__ int   g_is64;
__device__ int   g_deg[NN];
__device__ float g_dis[NN];
__device__ int   g_off[NN + 1];
__device__ int   g_cur[NN];
__device__ int   g_bsum[NB];
__device__ int   g_src32[EE];
__device__ int   g_dst32[EE];
__device__ int   g_srcs[EE];                       // CSR-sorted src per dst
__device__ uint4 g_x16[(size_t)NN * 32];           // fp16 dis-scaled [latent|cond], 512B/node
__device__ uint2 g_h16[(size_t)NN * 32];           // fp16 dis-scaled h2, 256B/node
__device__ float g_xagg[(size_t)NN * 256];         // aggregated [latent|condition] fp32
__device__ float g_act [(size_t)NN * 512];         // tanh(conv1|conv2) activations

// ==================== warp-MMA helpers (sm_80+ HMMA path) ====================
__device__ __forceinline__ uint32_t smem_u32(const void* p) {
    uint32_t a;
    asm("{ .reg .u64 t; cvta.to.shared.u64 t, %1; cvt.u32.u64 %0, t; }" : "=r"(a) : "l"(p));
    return a;
}

__device__ __forceinline__ void mma16816(float* d, const uint32_t* a, const uint32_t* b) {
    asm volatile(
        "mma.sync.aligned.m16n8k16.row.col.f32.bf16.bf16.f32 "
        "{%0,%1,%2,%3}, {%4,%5,%6,%7}, {%8,%9}, {%0,%1,%2,%3};"
        : "+f"(d[0]), "+f"(d[1]), "+f"(d[2]), "+f"(d[3])
        : "r"(a[0]), "r"(a[1]), "r"(a[2]), "r"(a[3]), "r"(b[0]), "r"(b[1]));
}

__device__ __forceinline__ void ldmx4(uint32_t* r, uint32_t addr) {
    asm volatile("ldmatrix.sync.aligned.m8n8.x4.shared.b16 {%0,%1,%2,%3}, [%4];"
                 : "=r"(r[0]), "=r"(r[1]), "=r"(r[2]), "=r"(r[3]) : "r"(addr));
}
__device__ __forceinline__ void ldmx4t(uint32_t* r, uint32_t addr) {
    asm volatile("ldmatrix.sync.aligned.m8n8.x4.trans.shared.b16 {%0,%1,%2,%3}, [%4];"
                 : "=r"(r[0]), "=r"(r[1]), "=r"(r[2]), "=r"(r[3]) : "r"(addr));
}

// pack fp32x4 -> (hi bf16x4, lo bf16x4)
__device__ __forceinline__ void split4(float4 v, uint2& uh, uint2& ul) {
    __nv_bfloat16 h0 = __float2bfloat16(v.x);
    __nv_bfloat16 h1 = __float2bfloat16(v.y);
    __nv_bfloat16 h2 = __float2bfloat16(v.z);
    __nv_bfloat16 h3 = __float2bfloat16(v.w);
    __nv_bfloat16 l0 = __float2bfloat16(v.x - __bfloat162float(h0));
    __nv_bfloat16 l1 = __float2bfloat16(v.y - __bfloat162float(h1));
    __nv_bfloat16 l2 = __float2bfloat16(v.z - __bfloat162float(h2));
    __nv_bfloat16 l3 = __float2bfloat16(v.w - __bfloat162float(h3));
    uh.x = ((uint32_t)__bfloat16_as_ushort(h1) << 16) | __bfloat16_as_ushort(h0);
    uh.y = ((uint32_t)__bfloat16_as_ushort(h3) << 16) | __bfloat16_as_ushort(h2);
    ul.x = ((uint32_t)__bfloat16_as_ushort(l1) << 16) | __bfloat16_as_ushort(l0);
    ul.y = ((uint32_t)__bfloat16_as_ushort(l3) << 16) | __bfloat16_as_ushort(l2);
}

// ==================== bf16x3 GEMM: 128x128 block, 8 warps of 32x64 ====================
// A: [NN, LDA] fp32 row-major. W: [KTOT, ldw] fp32 (read at ncol0). Output:
//   H16 ? g_h16[row] = half2(dis[row] * (A@W))  :  C[row] = op(A@W + bias) fp32
template <int KTOT, int LDA, int LDC, bool TANH, bool HASB, bool H16>
__device__ __forceinline__ void gemm_mma(const float* __restrict__ A,
                                         const float* __restrict__ W, int ldw,
                                         const float* __restrict__ bias,
                                         float* __restrict__ C,
                                         int row0, int ncol0) {
    __shared__ __align__(16) uint16_t sAh[128 * 40], sAl[128 * 40];  // stride 40 halves
    __shared__ __align__(16) uint16_t sBh[32 * 136], sBl[32 * 136];  // stride 136 halves

    int tid = threadIdx.x, lane = tid & 31, wid = tid >> 5;
    int wm = wid & 3, wn = wid >> 2;  // warp tile: rows [wm*32,+32), cols [wn*64,+64)

    float acc[2][8][4];
    #pragma unroll
    for (int i = 0; i < 2; i++)
        #pragma unroll
        for (int j = 0; j < 8; j++)
            #pragma unroll
            for (int k = 0; k < 4; k++) acc[i][j][k] = 0.f;

    uint32_t aAh = smem_u32(sAh), aAl = smem_u32(sAl);
    uint32_t aBh = smem_u32(sBh), aBl = smem_u32(sBl);
    uint32_t offA0 = (uint32_t)(((wm * 32 + (lane & 15)) * 40 + ((lane >> 4) << 3)) * 2);
    uint32_t offB0 = (uint32_t)(((lane & 15) * 136 + wn * 64 + ((lane >> 4) << 3)) * 2);

    for (int k0 = 0; k0 < KTOT; k0 += 32) {
        #pragma unroll
        for (int i = 0; i < 4; i++) {
            int lin = tid + 256 * i;
            int r = lin >> 3, c4 = lin & 7;
            int gr = row0 + r;
            float4 v = make_float4(0.f, 0.f, 0.f, 0.f);
            if (gr < NN) v = *(const float4*)(A + (size_t)gr * LDA + k0 + c4 * 4);
            uint2 uh, ul;
            split4(v, uh, ul);
            *(uint2*)((char*)sAh + (r * 40 + c4 * 4) * 2) = uh;
            *(uint2*)((char*)sAl + (r * 40 + c4 * 4) * 2) = ul;
        }
        #pragma unroll
        for (int i = 0; i < 4; i++) {
            int lin = tid + 256 * i;
            int kr = lin >> 5, c4 = lin & 31;
            float4 v = *(const float4*)(W + (size_t)(k0 + kr) * ldw + ncol0 + c4 * 4);
            uint2 uh, ul;
            split4(v, uh, ul);
            *(uint2*)((char*)sBh + (kr * 136 + c4 * 4) * 2) = uh;
            *(uint2*)((char*)sBl + (kr * 136 + c4 * 4) * 2) = ul;
        }
        __syncthreads();
        #pragma unroll
        for (int kb = 0; kb < 32; kb += 16) {
            uint32_t ah[2][4], al[2][4], bb[4][4];
            #pragma unroll
            for (int mi = 0; mi < 2; mi++) {
                uint32_t off = offA0 + (uint32_t)((mi * 16 * 40 + kb) * 2);
                ldmx4(ah[mi], aAh + off);
                ldmx4(al[mi], aAl + off);
            }
            #pragma unroll
            for (int g = 0; g < 4; g++)
                ldmx4t(bb[g], aBh + offB0 + (uint32_t)((kb * 136 + g * 16) * 2));
            #pragma unroll
            for (int mi = 0; mi < 2; mi++)
                #pragma unroll
                for (int g = 0; g < 4; g++) {
                    mma16816(acc[mi][2 * g],     ah[mi], &bb[g][0]);
                    mma16816(acc[mi][2 * g + 1], ah[mi], &bb[g][2]);
                    mma16816(acc[mi][2 * g],     al[mi], &bb[g][0]);
                    mma16816(acc[mi][2 * g + 1], al[mi], &bb[g][2]);
                }
            #pragma unroll
            for (int g = 0; g < 4; g++)
                ldmx4t(bb[g], aBl + offB0 + (uint32_t)((kb * 136 + g * 16) * 2));
            #pragma unroll
            for (int mi = 0; mi < 2; mi++)
                #pragma unroll
                for (int g = 0; g < 4; g++) {
                    mma16816(acc[mi][2 * g],     ah[mi], &bb[g][0]);
                    mma16816(acc[mi][2 * g + 1], ah[mi], &bb[g][2]);
                }
        }
        __syncthreads();
    }

    // ---- epilogue
    int rbase = row0 + wm * 32 + (lane >> 2);
    #pragma unroll
    for (int mi = 0; mi < 2; mi++)
        #pragma unroll
        for (int h = 0; h < 2; h++) {
            int gr = rbase + mi * 16 + h * 8;
            if (gr >= NN) continue;
            float dd = H16 ? g_dis[gr] : 0.f;
            #pragma unroll
            for (int ni = 0; ni < 8; ni++) {
                int cl = wn * 64 + ni * 8 + (lane & 3) * 2;
                float v0 = acc[mi][ni][2 * h];
                float v1 = acc[mi][ni][2 * h + 1];
                if (HASB) { v0 += bias[cl]; v1 += bias[cl + 1]; }
                if (TANH) { v0 = tanhf(v0); v1 = tanhf(v1); }
                if (H16) {
                    __half2 p = __floats2half2_rn(dd * v0, dd * v1);
                    ((__half2*)g_h16)[(size_t)gr * 64 + (cl >> 1)] = p;
                } else {
                    *(float2*)(C + (size_t)gr * LDC + cl) = make_float2(v0, v1);
                }
            }
        }
}

__global__ void __launch_bounds__(256, 2) gemm_zc_mma(const float* __restrict__ Wz,
                                                      const float* __restrict__ bz,
                                                      const float* __restrict__ Wc,
                                                      const float* __restrict__ bc) {
    int conv = blockIdx.z;
    int nb = blockIdx.y * 128;
    const float* W = conv ? Wc : Wz;
    const float* b = conv ? bc : bz;
    gemm_mma<128, 256, 512, true, true, false>(g_xagg + conv * 128, W, 256, b + nb,
                                               g_act + conv * 256 + nb, blockIdx.x * 128, nb);
}

__global__ void __launch_bounds__(256, 2) gemm_o_mma(const float* __restrict__ Wo) {
    gemm_mma<512, 512, 128, false, false, true>(g_act, Wo, 128, nullptr,
                                                nullptr, blockIdx.x * 128, 0);
}

// ---------------- dtype detection: int64 vs int32 edge_index ----------------
__global__ void detect_kernel(const unsigned int* __restrict__ w) {
    __shared__ int ok;
    if (threadIdx.x == 0) ok = 1;
    __syncthreads();
    for (int k = threadIdx.x; k < 2048; k += blockDim.x) {
        if (w[2 * k + 1] != 0u) ok = 0;
    }
    __syncthreads();
    if (threadIdx.x == 0) g_is64 = ok;
}

// convert + degree count fused (deg pre-initialized to 1 for self loop)
__global__ void convert_kernel(const void* __restrict__ ei) {
    int e = blockIdx.x * blockDim.x + threadIdx.x;
    if (e >= EE) return;
    int s, d;
    if (g_is64) {
        const long long* p = (const long long*)ei;
        s = (int)p[e];
        d = (int)p[EE + e];
    } else {
        const int* p = (const int*)ei;
        s = p[e];
        d = p[EE + e];
    }
    g_src32[e] = s;
    g_dst32[e] = d;
    atomicAdd(&g_deg[d], 1);
}

// ---------------- degree / norm / CSR build ----------------
__global__ void init_deg_kernel() {
    int i = blockIdx.x * blockDim.x + threadIdx.x;
    if (i < NN) g_deg[i] = 1;
}

__global__ void scan1_kernel() {
    __shared__ int sh[1024];
    int i = blockIdx.x * 1024 + threadIdx.x;
    int v = 0;
    if (i < NN) {
        int d = g_deg[i];
        g_dis[i] = rsqrtf((float)d);
        v = d - 1;
    }
    sh[threadIdx.x] = v;
    __syncthreads();
    for (int ofs = 1; ofs < 1024; ofs <<= 1) {
        int t = 0;
        if ((int)threadIdx.x >= ofs) t = sh[threadIdx.x - ofs];
        __syncthreads();
        sh[threadIdx.x] += t;
        __syncthreads();
    }
    int incl = sh[threadIdx.x];
    if (i < NN) g_off[i] = incl - v;
    if (threadIdx.x == 1023) g_bsum[blockIdx.x] = incl;
}

__global__ void scan2_kernel() {
    int run = 0;
    for (int b = 0; b < NB; b++) {
        int t = g_bsum[b];
        g_bsum[b] = run;
        run += t;
    }
}

__global__ void scan3_kernel() {
    int i = blockIdx.x * 1024 + threadIdx.x;
    if (i < NN) {
        int o = g_off[i] + g_bsum[blockIdx.x];
        g_off[i] = o;
        g_cur[i] = o;
    }
    if (i == 0) g_off[NN] = EE;
}

__global__ void scatter_kernel() {
    int e = blockIdx.x * blockDim.x + threadIdx.x;
    if (e < EE) {
        int d = g_dst32[e];
        int p = atomicAdd(&g_cur[d], 1);
        g_srcs[p] = g_src32[e];
    }
}

// ---------------- cast features to dis-scaled fp16, interleaved row ----------
__global__ void cast_kernel(const float* __restrict__ lat,
                            const float* __restrict__ cond) {
    int t = blockIdx.x * blockDim.x + threadIdx.x;  // over NN*128 half2 slots
    if (t >= NN * 128) return;
    int node = t >> 7;
    int c2 = t & 127;
    float dd = g_dis[node];
    float2 v;
    if (c2 < 64) v = ((const float2*)lat)[(size_t)node * 64 + c2];
    else         v = ((const float2*)cond)[(size_t)node * 64 + (c2 - 64)];
    ((__half2*)g_x16)[(size_t)t] = __floats2half2_rn(dd * v.x, dd * v.y);
}

// ---------------- unpack-accumulate helpers ----------------
__device__ __forceinline__ void acc8(float* a, uint4 v) {
    const __half2* h = (const __half2*)&v;
    #pragma unroll
    for (int k = 0; k < 4; k++) {
        float2 f = __half22float2(h[k]);
        a[2 * k] += f.x;
        a[2 * k + 1] += f.y;
    }
}
__device__ __forceinline__ void acc4(float* a, uint2 v) {
    const __half2* h = (const __half2*)&v;
    float2 f0 = __half22float2(h[0]);
    float2 f1 = __half22float2(h[1]);
    a[0] += f0.x; a[1] += f0.y; a[2] += f1.x; a[3] += f1.y;
}

// ---------------- aggregation 1: fp16 gather, 512B/node, warp-per-node -----
__global__ void __launch_bounds__(256) aggx_kernel() {
    int gw = (int)((blockIdx.x * blockDim.x + threadIdx.x) >> 5);
    int lane = threadIdx.x & 31;
    if (gw >= NN) return;
    float dd = g_dis[gw];
    float a[8];
    #pragma unroll
    for (int k = 0; k < 8; k++) a[k] = 0.f;
    acc8(a, g_x16[(size_t)gw * 32 + lane]);  // self term (pre-scaled by dis)
    int beg = g_off[gw], end = g_off[gw + 1];
    #pragma unroll 4
    for (int j = beg; j < end; ++j) {
        int s = g_srcs[j];
        acc8(a, g_x16[(size_t)s * 32 + lane]);
    }
    float4* O = (float4*)(g_xagg + (size_t)gw * 256 + lane * 8);
    O[0] = make_float4(dd * a[0], dd * a[1], dd * a[2], dd * a[3]);
    O[1] = make_float4(dd * a[4], dd * a[5], dd * a[6], dd * a[7]);
}

// ---------------- aggregation 2: fp16 gather, 256B/node, warp-per-node -----
__global__ void __launch_bounds__(256) agg2_kernel(const float* __restrict__ bo,
                                                   float* __restrict__ out) {
    int gw = (int)((blockIdx.x * blockDim.x + threadIdx.x) >> 5);
    int lane = threadIdx.x & 31;
    if (gw >= NN) return;
    float dd = g_dis[gw];
    float a[4];
    #pragma unroll
    for (int k = 0; k < 4; k++) a[k] = 0.f;
    acc4(a, g_h16[(size_t)gw * 32 + lane]);  // self term
    int beg = g_off[gw], end = g_off[gw + 1];
    #pragma unroll 4
    for (int j = beg; j < end; ++j) {
        int s = g_srcs[j];
        acc4(a, g_h16[(size_t)s * 32 + lane]);
    }
    float4 b = ((const float4*)bo)[lane];
    ((float4*)out)[(size_t)gw * 32 + lane] =
        make_float4(dd * a[0] + b.x, dd * a[1] + b.y, dd * a[2] + b.z, dd * a[3] + b.w);
}

// ---------------- launch ----------------
extern "C" void kernel_launch(void* const* d_in, const int* in_sizes, int n_in,
                              void* d_out, int out_size) {
    const float* latent    = (const float*)d_in[0];
    const float* condition = (const float*)d_in[1];
    const void*  ei        = d_in[2];
    const float* Wz = (const float*)d_in[3];
    const float* bz = (const float*)d_in[4];
    const float* Wc = (const float*)d_in[5];
    const float* bc = (const float*)d_in[6];
    const float* Wo = (const float*)d_in[7];
    const float* bo = (const float*)d_in[8];
    float* out = (float*)d_out;

    detect_kernel<<<1, 256>>>((const unsigned int*)ei);
    init_deg_kernel<<<(NN + 255) / 256, 256>>>();
    convert_kernel<<<(EE + 255) / 256, 256>>>(ei);
    scan1_kernel<<<NB, 1024>>>();
    scan2_kernel<<<1, 1>>>();
    scan3_kernel<<<NB, 1024>>>();
    scatter_kernel<<<(EE + 255) / 256, 256>>>();
    cast_kernel<<<(NN * 128 + 255) / 256, 256>>>(latent, condition);
    aggx_kernel<<<(NN * 32 + 255) / 256, 256>>>();

    int ntiles = (NN + 127) / 128;  // 782
    gemm_zc_mma<<<dim3(ntiles, 2, 2), 256>>>(Wz, bz, Wc, bc);
    gemm_o_mma<<<dim3(ntiles, 1, 1), 256>>>(Wo);

    agg2_kernel<<<(NN * 32 + 255) / 256, 256>>>(bo, out);
}

// round 7
// speedup vs baseline: 1.9782x; 1.0721x over previous
#include <cuda_runtime.h>
#include <cuda_bf16.h>
#include <cuda_fp16.h>
#include <cstdint>
#include <math.h>

#define NN 100000
#define EE 3200000
#define NB 98  // ceil(NN/1024)

// ---------------- device scratch (static, no runtime alloc) ----------------
__device__ int   g_is64;
__device__ int   g_deg[NN];
__device__ float g_dis[NN];
__device__ int   g_off[NN + 1];
__device__ int   g_cur[NN];
__device__ int   g_bsum[NB];
__device__ int   g_srcs[EE];                       // CSR-sorted src per dst
__device__ uint4 g_x16   [(size_t)NN * 32];        // fp16 dis-scaled [latent|cond]
__device__ uint4 g_xagg16[(size_t)NN * 32];        // fp16 aggregated features (256)
__device__ uint4 g_act16 [(size_t)NN * 64];        // fp16 tanh activations (512)
__device__ uint2 g_h16   [(size_t)NN * 32];        // fp16 dis-scaled h2 (128)

// ==================== warp-MMA helpers (sm_80+ HMMA path) ====================
__device__ __forceinline__ uint32_t smem_u32(const void* p) {
    uint32_t a;
    asm("{ .reg .u64 t; cvta.to.shared.u64 t, %1; cvt.u32.u64 %0, t; }" : "=r"(a) : "l"(p));
    return a;
}

__device__ __forceinline__ void mma16816(float* d, const uint32_t* a, const uint32_t* b) {
    asm volatile(
        "mma.sync.aligned.m16n8k16.row.col.f32.bf16.bf16.f32 "
        "{%0,%1,%2,%3}, {%4,%5,%6,%7}, {%8,%9}, {%0,%1,%2,%3};"
        : "+f"(d[0]), "+f"(d[1]), "+f"(d[2]), "+f"(d[3])
        : "r"(a[0]), "r"(a[1]), "r"(a[2]), "r"(a[3]), "r"(b[0]), "r"(b[1]));
}

__device__ __forceinline__ void ldmx4(uint32_t* r, uint32_t addr) {
    asm volatile("ldmatrix.sync.aligned.m8n8.x4.shared.b16 {%0,%1,%2,%3}, [%4];"
                 : "=r"(r[0]), "=r"(r[1]), "=r"(r[2]), "=r"(r[3]) : "r"(addr));
}
__device__ __forceinline__ void ldmx4t(uint32_t* r, uint32_t addr) {
    asm volatile("ldmatrix.sync.aligned.m8n8.x4.trans.shared.b16 {%0,%1,%2,%3}, [%4];"
                 : "=r"(r[0]), "=r"(r[1]), "=r"(r[2]), "=r"(r[3]) : "r"(addr));
}

// pack fp32x4 -> (hi bf16x4, lo bf16x4)
__device__ __forceinline__ void split4(float4 v, uint2& uh, uint2& ul) {
    __nv_bfloat16 h0 = __float2bfloat16(v.x);
    __nv_bfloat16 h1 = __float2bfloat16(v.y);
    __nv_bfloat16 h2 = __float2bfloat16(v.z);
    __nv_bfloat16 h3 = __float2bfloat16(v.w);
    __nv_bfloat16 l0 = __float2bfloat16(v.x - __bfloat162float(h0));
    __nv_bfloat16 l1 = __float2bfloat16(v.y - __bfloat162float(h1));
    __nv_bfloat16 l2 = __float2bfloat16(v.z - __bfloat162float(h2));
    __nv_bfloat16 l3 = __float2bfloat16(v.w - __bfloat162float(h3));
    uh.x = ((uint32_t)__bfloat16_as_ushort(h1) << 16) | __bfloat16_as_ushort(h0);
    uh.y = ((uint32_t)__bfloat16_as_ushort(h3) << 16) | __bfloat16_as_ushort(h2);
    ul.x = ((uint32_t)__bfloat16_as_ushort(l1) << 16) | __bfloat16_as_ushort(l0);
    ul.y = ((uint32_t)__bfloat16_as_ushort(l3) << 16) | __bfloat16_as_ushort(l2);
}

// 8 fp16 -> (8 bf16 hi, 8 bf16 lo) — exact decomposition of fp16 values
__device__ __forceinline__ void split8h(uint4 v, uint4& uh, uint4& ul) {
    const __half2* h = (const __half2*)&v;
    uint32_t* ph = (uint32_t*)&uh;
    uint32_t* pl = (uint32_t*)&ul;
    #pragma unroll
    for (int k = 0; k < 4; k++) {
        float2 f = __half22float2(h[k]);
        __nv_bfloat16 b0 = __float2bfloat16(f.x);
        __nv_bfloat16 b1 = __float2bfloat16(f.y);
        __nv_bfloat16 c0 = __float2bfloat16(f.x - __bfloat162float(b0));
        __nv_bfloat16 c1 = __float2bfloat16(f.y - __bfloat162float(b1));
        ph[k] = ((uint32_t)__bfloat16_as_ushort(b1) << 16) | __bfloat16_as_ushort(b0);
        pl[k] = ((uint32_t)__bfloat16_as_ushort(c1) << 16) | __bfloat16_as_ushort(c0);
    }
}

// ==================== bf16x3 GEMM: 128x128 block, 8 warps of 32x64 ====================
// A: [NN, LDA] fp16 row-major (exact bf16 hi/lo split). W: [KTOT, ldw] fp32 @ncol0.
// Output: H16 ? g_h16[row] = half2(dis[row]*(A@W)) : C[row] = half2(op(A@W + bias))
template <int KTOT, int LDA, int LDC, bool TANH, bool HASB, bool H16>
__device__ __forceinline__ void gemm_mma(const __half* __restrict__ A,
                                         const float* __restrict__ W, int ldw,
                                         const float* __restrict__ bias,
                                         __half* __restrict__ C,
                                         int row0, int ncol0) {
    __shared__ __align__(16) uint16_t sAh[128 * 40], sAl[128 * 40];  // stride 40 halves
    __shared__ __align__(16) uint16_t sBh[32 * 136], sBl[32 * 136];  // stride 136 halves

    int tid = threadIdx.x, lane = tid & 31, wid = tid >> 5;
    int wm = wid & 3, wn = wid >> 2;  // warp tile: rows [wm*32,+32), cols [wn*64,+64)

    float acc[2][8][4];
    #pragma unroll
    for (int i = 0; i < 2; i++)
        #pragma unroll
        for (int j = 0; j < 8; j++)
            #pragma unroll
            for (int k = 0; k < 4; k++) acc[i][j][k] = 0.f;

    uint32_t aAh = smem_u32(sAh), aAl = smem_u32(sAl);
    uint32_t aBh = smem_u32(sBh), aBl = smem_u32(sBl);
    uint32_t offA0 = (uint32_t)(((wm * 32 + (lane & 15)) * 40 + ((lane >> 4) << 3)) * 2);
    uint32_t offB0 = (uint32_t)(((lane & 15) * 136 + wn * 64 + ((lane >> 4) << 3)) * 2);

    for (int k0 = 0; k0 < KTOT; k0 += 32) {
        // ---- stage A chunk [128 x 32] fp16 -> hi/lo bf16
        #pragma unroll
        for (int i = 0; i < 2; i++) {
            int lin = tid + 256 * i;             // 0..511
            int r = lin >> 2, c8 = lin & 3;      // 8 halves per thread-slot
            int gr = row0 + r;
            uint4 v = make_uint4(0u, 0u, 0u, 0u);
            if (gr < NN) v = *(const uint4*)(A + (size_t)gr * LDA + k0 + c8 * 8);
            uint4 uh, ul;
            split8h(v, uh, ul);
            *(uint4*)((char*)sAh + (r * 40 + c8 * 8) * 2) = uh;
            *(uint4*)((char*)sAl + (r * 40 + c8 * 8) * 2) = ul;
        }
        // ---- stage B chunk [32 x 128] from fp32 W
        #pragma unroll
        for (int i = 0; i < 4; i++) {
            int lin = tid + 256 * i;
            int kr = lin >> 5, c4 = lin & 31;
            float4 v = *(const float4*)(W + (size_t)(k0 + kr) * ldw + ncol0 + c4 * 4);
            uint2 uh, ul;
            split4(v, uh, ul);
            *(uint2*)((char*)sBh + (kr * 136 + c4 * 4) * 2) = uh;
            *(uint2*)((char*)sBl + (kr * 136 + c4 * 4) * 2) = ul;
        }
        __syncthreads();
        #pragma unroll
        for (int kb = 0; kb < 32; kb += 16) {
            uint32_t ah[2][4], al[2][4], bb[4][4];
            #pragma unroll
            for (int mi = 0; mi < 2; mi++) {
                uint32_t off = offA0 + (uint32_t)((mi * 16 * 40 + kb) * 2);
                ldmx4(ah[mi], aAh + off);
                ldmx4(al[mi], aAl + off);
            }
            #pragma unroll
            for (int g = 0; g < 4; g++)
                ldmx4t(bb[g], aBh + offB0 + (uint32_t)((kb * 136 + g * 16) * 2));
            #pragma unroll
            for (int mi = 0; mi < 2; mi++)
                #pragma unroll
                for (int g = 0; g < 4; g++) {
                    mma16816(acc[mi][2 * g],     ah[mi], &bb[g][0]);
                    mma16816(acc[mi][2 * g + 1], ah[mi], &bb[g][2]);
                    mma16816(acc[mi][2 * g],     al[mi], &bb[g][0]);
                    mma16816(acc[mi][2 * g + 1], al[mi], &bb[g][2]);
                }
            #pragma unroll
            for (int g = 0; g < 4; g++)
                ldmx4t(bb[g], aBl + offB0 + (uint32_t)((kb * 136 + g * 16) * 2));
            #pragma unroll
            for (int mi = 0; mi < 2; mi++)
                #pragma unroll
                for (int g = 0; g < 4; g++) {
                    mma16816(acc[mi][2 * g],     ah[mi], &bb[g][0]);
                    mma16816(acc[mi][2 * g + 1], ah[mi], &bb[g][2]);
                }
        }
        __syncthreads();
    }

    // ---- epilogue: half2 outputs
    int rbase = row0 + wm * 32 + (lane >> 2);
    #pragma unroll
    for (int mi = 0; mi < 2; mi++)
        #pragma unroll
        for (int h = 0; h < 2; h++) {
            int gr = rbase + mi * 16 + h * 8;
            if (gr >= NN) continue;
            float dd = H16 ? g_dis[gr] : 1.f;
            #pragma unroll
            for (int ni = 0; ni < 8; ni++) {
                int cl = wn * 64 + ni * 8 + (lane & 3) * 2;
                float v0 = acc[mi][ni][2 * h];
                float v1 = acc[mi][ni][2 * h + 1];
                if (HASB) { v0 += bias[cl]; v1 += bias[cl + 1]; }
                if (TANH) { v0 = tanhf(v0); v1 = tanhf(v1); }
                if (H16) {
                    ((__half2*)g_h16)[(size_t)gr * 64 + (cl >> 1)] =
                        __floats2half2_rn(dd * v0, dd * v1);
                } else {
                    *(__half2*)(C + (size_t)gr * LDC + cl) = __floats2half2_rn(v0, v1);
                }
            }
        }
}

__global__ void __launch_bounds__(256, 2) gemm_zc_mma(const float* __restrict__ Wz,
                                                      const float* __restrict__ bz,
                                                      const float* __restrict__ Wc,
                                                      const float* __restrict__ bc) {
    int conv = blockIdx.z;
    int nb = blockIdx.y * 128;
    const float* W = conv ? Wc : Wz;
    const float* b = conv ? bc : bz;
    gemm_mma<128, 256, 512, true, true, false>(
        (const __half*)g_xagg16 + conv * 128, W, 256, b + nb,
        (__half*)g_act16 + conv * 256 + nb, blockIdx.x * 128, nb);
}

__global__ void __launch_bounds__(256, 2) gemm_o_mma(const float* __restrict__ Wo) {
    gemm_mma<512, 512, 128, false, false, true>(
        (const __half*)g_act16, Wo, 128, nullptr, nullptr, blockIdx.x * 128, 0);
}

// ---------------- dtype detection: int64 vs int32 edge_index ----------------
__global__ void detect_kernel(const unsigned int* __restrict__ w) {
    __shared__ int ok;
    if (threadIdx.x == 0) ok = 1;
    __syncthreads();
    for (int k = threadIdx.x; k < 2048; k += blockDim.x) {
        if (w[2 * k + 1] != 0u) ok = 0;
    }
    __syncthreads();
    if (threadIdx.x == 0) g_is64 = ok;
}

// ---------------- degree / norm / CSR build ----------------
__global__ void init_deg_kernel() {
    int i = blockIdx.x * blockDim.x + threadIdx.x;
    if (i < NN) g_deg[i] = 1;  // self loop pre-counted
}

__global__ void count_kernel(const void* __restrict__ ei) {
    int e = blockIdx.x * blockDim.x + threadIdx.x;
    if (e >= EE) return;
    int d = g_is64 ? (int)((const long long*)ei)[EE + e] : ((const int*)ei)[EE + e];
    atomicAdd(&g_deg[d], 1);
}

__global__ void scan1_kernel() {
    __shared__ int sh[1024];
    int i = blockIdx.x * 1024 + threadIdx.x;
    int v = 0;
    if (i < NN) {
        int d = g_deg[i];
        g_dis[i] = rsqrtf((float)d);
        v = d - 1;
    }
    sh[threadIdx.x] = v;
    __syncthreads();
    for (int ofs = 1; ofs < 1024; ofs <<= 1) {
        int t = 0;
        if ((int)threadIdx.x >= ofs) t = sh[threadIdx.x - ofs];
        __syncthreads();
        sh[threadIdx.x] += t;
        __syncthreads();
    }
    int incl = sh[threadIdx.x];
    if (i < NN) g_off[i] = incl - v;
    if (threadIdx.x == 1023) g_bsum[blockIdx.x] = incl;
}

__global__ void scan2_kernel() {
    int run = 0;
    for (int b = 0; b < NB; b++) {
        int t = g_bsum[b];
        g_bsum[b] = run;
        run += t;
    }
}

__global__ void scan3_kernel() {
    int i = blockIdx.x * 1024 + threadIdx.x;
    if (i < NN) {
        int o = g_off[i] + g_bsum[blockIdx.x];
        g_off[i] = o;
        g_cur[i] = o;
    }
    if (i == 0) g_off[NN] = EE;
}

__global__ void scatter_kernel(const void* __restrict__ ei) {
    int e = blockIdx.x * blockDim.x + threadIdx.x;
    if (e >= EE) return;
    int s, d;
    if (g_is64) {
        const long long* p = (const long long*)ei;
        s = (int)p[e];
        d = (int)p[EE + e];
    } else {
        const int* p = (const int*)ei;
        s = p[e];
        d = p[EE + e];
    }
    int pos = atomicAdd(&g_cur[d], 1);
    g_srcs[pos] = s;
}

// ---------------- cast features to dis-scaled fp16, interleaved row ----------
__global__ void cast_kernel(const float* __restrict__ lat,
                            const float* __restrict__ cond) {
    int t = blockIdx.x * blockDim.x + threadIdx.x;  // over NN*128 half2 slots
    if (t >= NN * 128) return;
    int node = t >> 7;
    int c2 = t & 127;
    float dd = g_dis[node];
    float2 v;
    if (c2 < 64) v = ((const float2*)lat)[(size_t)node * 64 + c2];
    else         v = ((const float2*)cond)[(size_t)node * 64 + (c2 - 64)];
    ((__half2*)g_x16)[(size_t)t] = __floats2half2_rn(dd * v.x, dd * v.y);
}

// ---------------- unpack-accumulate helpers ----------------
__device__ __forceinline__ void acc8(float* a, uint4 v) {
    const __half2* h = (const __half2*)&v;
    #pragma unroll
    for (int k = 0; k < 4; k++) {
        float2 f = __half22float2(h[k]);
        a[2 * k] += f.x;
        a[2 * k + 1] += f.y;
    }
}
__device__ __forceinline__ void acc4(float* a, uint2 v) {
    const __half2* h = (const __half2*)&v;
    float2 f0 = __half22float2(h[0]);
    float2 f1 = __half22float2(h[1]);
    a[0] += f0.x; a[1] += f0.y; a[2] += f1.x; a[3] += f1.y;
}

// ---------------- aggregation 1: fp16 gather, 512B/node, warp-per-node -----
__global__ void __launch_bounds__(256) aggx_kernel() {
    int gw = (int)((blockIdx.x * blockDim.x + threadIdx.x) >> 5);
    int lane = threadIdx.x & 31;
    if (gw >= NN) return;
    float dd = g_dis[gw];
    float a[8];
    #pragma unroll
    for (int k = 0; k < 8; k++) a[k] = 0.f;
    acc8(a, g_x16[(size_t)gw * 32 + lane]);  // self term (pre-scaled by dis)
    int beg = g_off[gw], end = g_off[gw + 1];
    #pragma unroll 4
    for (int j = beg; j < end; ++j) {
        int s = g_srcs[j];
        acc8(a, g_x16[(size_t)s * 32 + lane]);
    }
    uint4 o;
    __half2* oh = (__half2*)&o;
    #pragma unroll
    for (int k = 0; k < 4; k++)
        oh[k] = __floats2half2_rn(dd * a[2 * k], dd * a[2 * k + 1]);
    g_xagg16[(size_t)gw * 32 + lane] = o;
}

// ---------------- aggregation 2: fp16 gather, 256B/node, warp-per-node -----
__global__ void __launch_bounds__(256) agg2_kernel(const float* __restrict__ bo,
                                                   float* __restrict__ out) {
    int gw = (int)((blockIdx.x * blockDim.x + threadIdx.x) >> 5);
    int lane = threadIdx.x & 31;
    if (gw >= NN) return;
    float dd = g_dis[gw];
    float a[4];
    #pragma unroll
    for (int k = 0; k < 4; k++) a[k] = 0.f;
    acc4(a, g_h16[(size_t)gw * 32 + lane]);  // self term
    int beg = g_off[gw], end = g_off[gw + 1];
    #pragma unroll 4
    for (int j = beg; j < end; ++j) {
        int s = g_srcs[j];
        acc4(a, g_h16[(size_t)s * 32 + lane]);
    }
    float4 b = ((const float4*)bo)[lane];
    ((float4*)out)[(size_t)gw * 32 + lane] =
        make_float4(dd * a[0] + b.x, dd * a[1] + b.y, dd * a[2] + b.z, dd * a[3] + b.w);
}

// ---------------- launch ----------------
extern "C" void kernel_launch(void* const* d_in, const int* in_sizes, int n_in,
                              void* d_out, int out_size) {
    const float* latent    = (const float*)d_in[0];
    const float* condition = (const float*)d_in[1];
    const void*  ei        = d_in[2];
    const float* Wz = (const float*)d_in[3];
    const float* bz = (const float*)d_in[4];
    const float* Wc = (const float*)d_in[5];
    const float* bc = (const float*)d_in[6];
    const float* Wo = (const float*)d_in[7];
    const float* bo = (const float*)d_in[8];
    float* out = (float*)d_out;

    detect_kernel<<<1, 256>>>((const unsigned int*)ei);
    init_deg_kernel<<<(NN + 255) / 256, 256>>>();
    count_kernel<<<(EE + 255) / 256, 256>>>(ei);
    scan1_kernel<<<NB, 1024>>>();
    scan2_kernel<<<1, 1>>>();
    scan3_kernel<<<NB, 1024>>>();
    scatter_kernel<<<(EE + 255) / 256, 256>>>(ei);
    cast_kernel<<<(NN * 128 + 255) / 256, 256>>>(latent, condition);
    aggx_kernel<<<(NN * 32 + 255) / 256, 256>>>();

    int ntiles = (NN + 127) / 128;  // 782
    gemm_zc_mma<<<dim3(ntiles, 2, 2), 256>>>(Wz, bz, Wc, bc);
    gemm_o_mma<<<dim3(ntiles, 1, 1), 256>>>(Wo);

    agg2_kernel<<<(NN * 32 + 255) / 256, 256>>>(bo, out);
}

// round 8
// speedup vs baseline: 2.2212x; 1.1229x over previous
#include <cuda_runtime.h>
#include <cuda_bf16.h>
#include <cuda_fp16.h>
#include <cstdint>
#include <math.h>

#define NN 100000
#define EE 3200000
#define NB 98  // ceil(NN/1024)

// ---------------- device scratch (static, no runtime alloc) ----------------
__device__ int   g_is64;
__device__ int   g_deg[NN];
__device__ float g_dis[NN];
__device__ int   g_off[NN + 1];
__device__ int   g_cur[NN];
__device__ int   g_bsum[NB];
__device__ int   g_srcs[EE];                       // CSR-sorted src per dst
__device__ uint4 g_x16   [(size_t)NN * 32];        // fp16 dis-scaled [latent|cond]
__device__ uint4 g_xagg16[(size_t)NN * 32];        // fp16 aggregated features (256)
__device__ uint4 g_act16 [(size_t)NN * 64];        // fp16 tanh activations (512)
__device__ uint2 g_h16   [(size_t)NN * 32];        // fp16 dis-scaled h2 (128)

// ==================== warp-MMA helpers (sm_80+ HMMA path) ====================
__device__ __forceinline__ uint32_t smem_u32(const void* p) {
    uint32_t a;
    asm("{ .reg .u64 t; cvta.to.shared.u64 t, %1; cvt.u32.u64 %0, t; }" : "=r"(a) : "l"(p));
    return a;
}

// fp16 x fp16 -> fp32 accumulate
__device__ __forceinline__ void mma16816h(float* d, const uint32_t* a, const uint32_t* b) {
    asm volatile(
        "mma.sync.aligned.m16n8k16.row.col.f32.f16.f16.f32 "
        "{%0,%1,%2,%3}, {%4,%5,%6,%7}, {%8,%9}, {%0,%1,%2,%3};"
        : "+f"(d[0]), "+f"(d[1]), "+f"(d[2]), "+f"(d[3])
        : "r"(a[0]), "r"(a[1]), "r"(a[2]), "r"(a[3]), "r"(b[0]), "r"(b[1]));
}

__device__ __forceinline__ void ldmx4(uint32_t* r, uint32_t addr) {
    asm volatile("ldmatrix.sync.aligned.m8n8.x4.shared.b16 {%0,%1,%2,%3}, [%4];"
                 : "=r"(r[0]), "=r"(r[1]), "=r"(r[2]), "=r"(r[3]) : "r"(addr));
}
__device__ __forceinline__ void ldmx4t(uint32_t* r, uint32_t addr) {
    asm volatile("ldmatrix.sync.aligned.m8n8.x4.trans.shared.b16 {%0,%1,%2,%3}, [%4];"
                 : "=r"(r[0]), "=r"(r[1]), "=r"(r[2]), "=r"(r[3]) : "r"(addr));
}

// pack fp32x4 -> (hi fp16x4, residual fp16x4): v = hi + lo to ~22 significand bits
__device__ __forceinline__ void splitw4(float4 v, uint2& uh, uint2& ul) {
    __half h0 = __float2half_rn(v.x);
    __half h1 = __float2half_rn(v.y);
    __half h2 = __float2half_rn(v.z);
    __half h3 = __float2half_rn(v.w);
    __half l0 = __float2half_rn(v.x - __half2float(h0));
    __half l1 = __float2half_rn(v.y - __half2float(h1));
    __half l2 = __float2half_rn(v.z - __half2float(h2));
    __half l3 = __float2half_rn(v.w - __half2float(h3));
    uh.x = ((uint32_t)__half_as_ushort(h1) << 16) | __half_as_ushort(h0);
    uh.y = ((uint32_t)__half_as_ushort(h3) << 16) | __half_as_ushort(h2);
    ul.x = ((uint32_t)__half_as_ushort(l1) << 16) | __half_as_ushort(l0);
    ul.y = ((uint32_t)__half_as_ushort(l3) << 16) | __half_as_ushort(l2);
}

// ==================== fp16x2 GEMM: 128x128 block, 8 warps of 32x64 ====================
// A: [NN, LDA] fp16 row-major (exact fp16 operand). W: [KTOT, ldw] fp32 @ncol0,
// split into fp16 hi + fp16 residual. D = A@Wh + A@Wl in fp32 accumulators.
// Output: H16 ? g_h16[row] = half2(dis[row]*(A@W)) : C[row] = half2(op(A@W + bias))
template <int KTOT, int LDA, int LDC, bool TANH, bool HASB, bool H16>
__device__ __forceinline__ void gemm_mma(const __half* __restrict__ A,
                                         const float* __restrict__ W, int ldw,
                                         const float* __restrict__ bias,
                                         __half* __restrict__ C,
                                         int row0, int ncol0) {
    __shared__ __align__(16) uint16_t sA [128 * 40];                 // stride 40 halves
    __shared__ __align__(16) uint16_t sBh[32 * 136], sBl[32 * 136];  // stride 136 halves

    int tid = threadIdx.x, lane = tid & 31, wid = tid >> 5;
    int wm = wid & 3, wn = wid >> 2;  // warp tile: rows [wm*32,+32), cols [wn*64,+64)

    float acc[2][8][4];
    #pragma unroll
    for (int i = 0; i < 2; i++)
        #pragma unroll
        for (int j = 0; j < 8; j++)
            #pragma unroll
            for (int k = 0; k < 4; k++) acc[i][j][k] = 0.f;

    uint32_t aA = smem_u32(sA);
    uint32_t aBh = smem_u32(sBh), aBl = smem_u32(sBl);
    uint32_t offA0 = (uint32_t)(((wm * 32 + (lane & 15)) * 40 + ((lane >> 4) << 3)) * 2);
    uint32_t offB0 = (uint32_t)(((lane & 15) * 136 + wn * 64 + ((lane >> 4) << 3)) * 2);

    for (int k0 = 0; k0 < KTOT; k0 += 32) {
        // ---- stage A chunk [128 x 32] fp16 (single plane, no split)
        #pragma unroll
        for (int i = 0; i < 2; i++) {
            int lin = tid + 256 * i;             // 0..511
            int r = lin >> 2, c8 = lin & 3;      // 8 halves per slot
            int gr = row0 + r;
            uint4 v = make_uint4(0u, 0u, 0u, 0u);
            if (gr < NN) v = *(const uint4*)(A + (size_t)gr * LDA + k0 + c8 * 8);
            *(uint4*)((char*)sA + (r * 40 + c8 * 8) * 2) = v;
        }
        // ---- stage B chunk [32 x 128] from fp32 W -> fp16 hi/lo
        #pragma unroll
        for (int i = 0; i < 4; i++) {
            int lin = tid + 256 * i;
            int kr = lin >> 5, c4 = lin & 31;
            float4 v = *(const float4*)(W + (size_t)(k0 + kr) * ldw + ncol0 + c4 * 4);
            uint2 uh, ul;
            splitw4(v, uh, ul);
            *(uint2*)((char*)sBh + (kr * 136 + c4 * 4) * 2) = uh;
            *(uint2*)((char*)sBl + (kr * 136 + c4 * 4) * 2) = ul;
        }
        __syncthreads();
        #pragma unroll
        for (int kb = 0; kb < 32; kb += 16) {
            uint32_t a[2][4], bb[4][4];
            #pragma unroll
            for (int mi = 0; mi < 2; mi++)
                ldmx4(a[mi], aA + offA0 + (uint32_t)((mi * 16 * 40 + kb) * 2));
            #pragma unroll
            for (int g = 0; g < 4; g++)
                ldmx4t(bb[g], aBh + offB0 + (uint32_t)((kb * 136 + g * 16) * 2));
            #pragma unroll
            for (int mi = 0; mi < 2; mi++)
                #pragma unroll
                for (int g = 0; g < 4; g++) {
                    mma16816h(acc[mi][2 * g],     a[mi], &bb[g][0]);
                    mma16816h(acc[mi][2 * g + 1], a[mi], &bb[g][2]);
                }
            #pragma unroll
            for (int g = 0; g < 4; g++)
                ldmx4t(bb[g], aBl + offB0 + (uint32_t)((kb * 136 + g * 16) * 2));
            #pragma unroll
            for (int mi = 0; mi < 2; mi++)
                #pragma unroll
                for (int g = 0; g < 4; g++) {
                    mma16816h(acc[mi][2 * g],     a[mi], &bb[g][0]);
                    mma16816h(acc[mi][2 * g + 1], a[mi], &bb[g][2]);
                }
        }
        __syncthreads();
    }

    // ---- epilogue: half2 outputs
    int rbase = row0 + wm * 32 + (lane >> 2);
    #pragma unroll
    for (int mi = 0; mi < 2; mi++)
        #pragma unroll
        for (int h = 0; h < 2; h++) {
            int gr = rbase + mi * 16 + h * 8;
            if (gr >= NN) continue;
            float dd = H16 ? g_dis[gr] : 1.f;
            #pragma unroll
            for (int ni = 0; ni < 8; ni++) {
                int cl = wn * 64 + ni * 8 + (lane & 3) * 2;
                float v0 = acc[mi][ni][2 * h];
                float v1 = acc[mi][ni][2 * h + 1];
                if (HASB) { v0 += bias[cl]; v1 += bias[cl + 1]; }
                if (TANH) { v0 = tanhf(v0); v1 = tanhf(v1); }
                if (H16) {
                    ((__half2*)g_h16)[(size_t)gr * 64 + (cl >> 1)] =
                        __floats2half2_rn(dd * v0, dd * v1);
                } else {
                    *(__half2*)(C + (size_t)gr * LDC + cl) = __floats2half2_rn(v0, v1);
                }
            }
        }
}

__global__ void __launch_bounds__(256, 2) gemm_zc_mma(const float* __restrict__ Wz,
                                                      const float* __restrict__ bz,
                                                      const float* __restrict__ Wc,
                                                      const float* __restrict__ bc) {
    int conv = blockIdx.z;
    int nb = blockIdx.y * 128;
    const float* W = conv ? Wc : Wz;
    const float* b = conv ? bc : bz;
    gemm_mma<128, 256, 512, true, true, false>(
        (const __half*)g_xagg16 + conv * 128, W, 256, b + nb,
        (__half*)g_act16 + conv * 256 + nb, blockIdx.x * 128, nb);
}

__global__ void __launch_bounds__(256, 2) gemm_o_mma(const float* __restrict__ Wo) {
    gemm_mma<512, 512, 128, false, false, true>(
        (const __half*)g_act16, Wo, 128, nullptr, nullptr, blockIdx.x * 128, 0);
}

// ---------------- fused dtype detect + degree init ----------------
__global__ void detect_init_kernel(const unsigned int* __restrict__ w) {
    int i = blockIdx.x * blockDim.x + threadIdx.x;
    if (i < NN) g_deg[i] = 1;  // self loop pre-counted
    if (blockIdx.x == 0) {
        // If int64 (LE), high word of every value (<100000) is 0; sample 2048.
        int bad = 0;
        for (int k = threadIdx.x; k < 2048; k += blockDim.x)
            if (w[2 * k + 1] != 0u) bad = 1;
        if (__syncthreads_or(bad)) {
            if (threadIdx.x == 0) g_is64 = 0;
        } else {
            if (threadIdx.x == 0) g_is64 = 1;
        }
    }
}

// ---------------- degree / norm / CSR build ----------------
__global__ void count_kernel(const void* __restrict__ ei) {
    int e = blockIdx.x * blockDim.x + threadIdx.x;
    if (e >= EE) return;
    int d = g_is64 ? (int)((const long long*)ei)[EE + e] : ((const int*)ei)[EE + e];
    atomicAdd(&g_deg[d], 1);
}

__global__ void scan1_kernel() {
    __shared__ int sh[1024];
    int i = blockIdx.x * 1024 + threadIdx.x;
    int v = 0;
    if (i < NN) {
        int d = g_deg[i];
        g_dis[i] = rsqrtf((float)d);
        v = d - 1;
    }
    sh[threadIdx.x] = v;
    __syncthreads();
    for (int ofs = 1; ofs < 1024; ofs <<= 1) {
        int t = 0;
        if ((int)threadIdx.x >= ofs) t = sh[threadIdx.x - ofs];
        __syncthreads();
        sh[threadIdx.x] += t;
        __syncthreads();
    }
    int incl = sh[threadIdx.x];
    if (i < NN) g_off[i] = incl - v;
    if (threadIdx.x == 1023) g_bsum[blockIdx.x] = incl;
}

__global__ void scan2_kernel() {
    int run = 0;
    for (int b = 0; b < NB; b++) {
        int t = g_bsum[b];
        g_bsum[b] = run;
        run += t;
    }
}

__global__ void scan3_kernel() {
    int i = blockIdx.x * 1024 + threadIdx.x;
    if (i < NN) {
        int o = g_off[i] + g_bsum[blockIdx.x];
        g_off[i] = o;
        g_cur[i] = o;
    }
    if (i == 0) g_off[NN] = EE;
}

__global__ void scatter_kernel(const void* __restrict__ ei) {
    int e = blockIdx.x * blockDim.x + threadIdx.x;
    if (e >= EE) return;
    int s, d;
    if (g_is64) {
        const long long* p = (const long long*)ei;
        s = (int)p[e];
        d = (int)p[EE + e];
    } else {
        const int* p = (const int*)ei;
        s = p[e];
        d = p[EE + e];
    }
    int pos = atomicAdd(&g_cur[d], 1);
    g_srcs[pos] = s;
}

// ---------------- cast features to dis-scaled fp16, interleaved row ----------
__global__ void cast_kernel(const float* __restrict__ lat,
                            const float* __restrict__ cond) {
    int t = blockIdx.x * blockDim.x + threadIdx.x;  // over NN*128 half2 slots
    if (t >= NN * 128) return;
    int node = t >> 7;
    int c2 = t & 127;
    float dd = g_dis[node];
    float2 v;
    if (c2 < 64) v = ((const float2*)lat)[(size_t)node * 64 + c2];
    else         v = ((const float2*)cond)[(size_t)node * 64 + (c2 - 64)];
    ((__half2*)g_x16)[(size_t)t] = __floats2half2_rn(dd * v.x, dd * v.y);
}

// ---------------- unpack-accumulate helpers ----------------
__device__ __forceinline__ void acc8(float* a, uint4 v) {
    const __half2* h = (const __half2*)&v;
    #pragma unroll
    for (int k = 0; k < 4; k++) {
        float2 f = __half22float2(h[k]);
        a[2 * k] += f.x;
        a[2 * k + 1] += f.y;
    }
}
__device__ __forceinline__ void acc4(float* a, uint2 v) {
    const __half2* h = (const __half2*)&v;
    float2 f0 = __half22float2(h[0]);
    float2 f1 = __half22float2(h[1]);
    a[0] += f0.x; a[1] += f0.y; a[2] += f1.x; a[3] += f1.y;
}

// ---------------- aggregation 1: fp16 gather, 512B/node, warp-per-node -----
__global__ void __launch_bounds__(256) aggx_kernel() {
    int gw = (int)((blockIdx.x * blockDim.x + threadIdx.x) >> 5);
    int lane = threadIdx.x & 31;
    if (gw >= NN) return;
    float dd = g_dis[gw];
    float a[8];
    #pragma unroll
    for (int k = 0; k < 8; k++) a[k] = 0.f;
    acc8(a, g_x16[(size_t)gw * 32 + lane]);  // self term (pre-scaled by dis)
    int beg = g_off[gw], end = g_off[gw + 1];
    #pragma unroll 4
    for (int j = beg; j < end; ++j) {
        int s = g_srcs[j];
        acc8(a, g_x16[(size_t)s * 32 + lane]);
    }
    uint4 o;
    __half2* oh = (__half2*)&o;
    #pragma unroll
    for (int k = 0; k < 4; k++)
        oh[k] = __floats2half2_rn(dd * a[2 * k], dd * a[2 * k + 1]);
    g_xagg16[(size_t)gw * 32 + lane] = o;
}

// ---------------- aggregation 2: fp16 gather, 256B/node, warp-per-node -----
__global__ void __launch_bounds__(256) agg2_kernel(const float* __restrict__ bo,
                                                   float* __restrict__ out) {
    int gw = (int)((blockIdx.x * blockDim.x + threadIdx.x) >> 5);
    int lane = threadIdx.x & 31;
    if (gw >= NN) return;
    float dd = g_dis[gw];
    float a[4];
    #pragma unroll
    for (int k = 0; k < 4; k++) a[k] = 0.f;
    acc4(a, g_h16[(size_t)gw * 32 + lane]);  // self term
    int beg = g_off[gw], end = g_off[gw + 1];
    #pragma unroll 4
    for (int j = beg; j < end; ++j) {
        int s = g_srcs[j];
        acc4(a, g_h16[(size_t)s * 32 + lane]);
    }
    float4 b = ((const float4*)bo)[lane];
    ((float4*)out)[(size_t)gw * 32 + lane] =
        make_float4(dd * a[0] + b.x, dd * a[1] + b.y, dd * a[2] + b.z, dd * a[3] + b.w);
}

// ---------------- launch ----------------
extern "C" void kernel_launch(void* const* d_in, const int* in_sizes, int n_in,
                              void* d_out, int out_size) {
    const float* latent    = (const float*)d_in[0];
    const float* condition = (const float*)d_in[1];
    const void*  ei        = d_in[2];
    const float* Wz = (const float*)d_in[3];
    const float* bz = (const float*)d_in[4];
    const float* Wc = (const float*)d_in[5];
    const float* bc = (const float*)d_in[6];
    const float* Wo = (const float*)d_in[7];
    const float* bo = (const float*)d_in[8];
    float* out = (float*)d_out;

    detect_init_kernel<<<(NN + 255) / 256, 256>>>((const unsigned int*)ei);
    count_kernel<<<(EE + 255) / 256, 256>>>(ei);
    scan1_kernel<<<NB, 1024>>>();
    scan2_kernel<<<1, 1>>>();
    scan3_kernel<<<NB, 1024>>>();
    scatter_kernel<<<(EE + 255) / 256, 256>>>(ei);
    cast_kernel<<<(NN * 128 + 255) / 256, 256>>>(latent, condition);
    aggx_kernel<<<(NN * 32 + 255) / 256, 256>>>();

    int ntiles = (NN + 127) / 128;  // 782
    gemm_zc_mma<<<dim3(ntiles, 2, 2), 256>>>(Wz, bz, Wc, bc);
    gemm_o_mma<<<dim3(ntiles, 1, 1), 256>>>(Wo);

    agg2_kernel<<<(NN * 32 + 255) / 256, 256>>>(bo, out);
}

// round 9
// speedup vs baseline: 2.5268x; 1.1376x over previous
#include <cuda_runtime.h>
#include <cuda_bf16.h>
#include <cuda_fp16.h>
#include <cstdint>
#include <math.h>

#define NN 100000
#define EE 3200000
#define NB 98  // ceil(NN/1024)

#define SCAT_BLOCKS ((EE + 255) / 256)     // 12500
#define CAST_BLOCKS ((NN * 128) / 256)     // 50000

// ---------------- device scratch (static, no runtime alloc) ----------------
__device__ int   g_is64;
__device__ int   g_deg[NN];
__device__ float g_dis[NN];
__device__ int   g_off[NN + 1];
__device__ int   g_cur[NN];
__device__ int   g_bsum[NB];
__device__ int   g_srcs[EE];                       // CSR-sorted src per dst
__device__ uint4 g_x16   [(size_t)NN * 32];        // fp16 dis-scaled [latent|cond]
__device__ uint4 g_xagg16[(size_t)NN * 32];        // fp16 aggregated features (256)
__device__ uint4 g_act16 [(size_t)NN * 64];        // fp16 tanh activations (512)
__device__ uint2 g_h16   [(size_t)NN * 32];        // fp16 dis-scaled h2 (128)

// ==================== warp-MMA helpers (sm_80+ HMMA path) ====================
__device__ __forceinline__ uint32_t smem_u32(const void* p) {
    uint32_t a;
    asm("{ .reg .u64 t; cvta.to.shared.u64 t, %1; cvt.u32.u64 %0, t; }" : "=r"(a) : "l"(p));
    return a;
}

// fp16 x fp16 -> fp32 accumulate
__device__ __forceinline__ void mma16816h(float* d, const uint32_t* a, const uint32_t* b) {
    asm volatile(
        "mma.sync.aligned.m16n8k16.row.col.f32.f16.f16.f32 "
        "{%0,%1,%2,%3}, {%4,%5,%6,%7}, {%8,%9}, {%0,%1,%2,%3};"
        : "+f"(d[0]), "+f"(d[1]), "+f"(d[2]), "+f"(d[3])
        : "r"(a[0]), "r"(a[1]), "r"(a[2]), "r"(a[3]), "r"(b[0]), "r"(b[1]));
}

__device__ __forceinline__ void ldmx4(uint32_t* r, uint32_t addr) {
    asm volatile("ldmatrix.sync.aligned.m8n8.x4.shared.b16 {%0,%1,%2,%3}, [%4];"
                 : "=r"(r[0]), "=r"(r[1]), "=r"(r[2]), "=r"(r[3]) : "r"(addr));
}
__device__ __forceinline__ void ldmx4t(uint32_t* r, uint32_t addr) {
    asm volatile("ldmatrix.sync.aligned.m8n8.x4.trans.shared.b16 {%0,%1,%2,%3}, [%4];"
                 : "=r"(r[0]), "=r"(r[1]), "=r"(r[2]), "=r"(r[3]) : "r"(addr));
}

// pack fp32x4 -> fp16x4 (round-to-nearest)
__device__ __forceinline__ uint2 pack4h(float4 v) {
    uint2 u;
    __half2 a = __floats2half2_rn(v.x, v.y);
    __half2 b = __floats2half2_rn(v.z, v.w);
    u.x = *(uint32_t*)&a;
    u.y = *(uint32_t*)&b;
    return u;
}

// ==================== fp16 GEMM: 128x128 block, 8 warps of 32x64 ====================
// A: [NN, LDA] fp16 row-major. W: [KTOT, ldw] fp32 @ncol0 -> fp16 RN.
// D = A@W in fp32 accumulators.
// Output: H16 ? g_h16[row] = half2(dis[row]*D) : C[row] = half2(op(D + bias))
template <int KTOT, int LDA, int LDC, bool TANH, bool HASB, bool H16>
__device__ __forceinline__ void gemm_mma(const __half* __restrict__ A,
                                         const float* __restrict__ W, int ldw,
                                         const float* __restrict__ bias,
                                         __half* __restrict__ C,
                                         int row0, int ncol0) {
    __shared__ __align__(16) uint16_t sA[128 * 40];   // stride 40 halves
    __shared__ __align__(16) uint16_t sB[32 * 136];   // stride 136 halves

    int tid = threadIdx.x, lane = tid & 31, wid = tid >> 5;
    int wm = wid & 3, wn = wid >> 2;  // warp tile: rows [wm*32,+32), cols [wn*64,+64)

    float acc[2][8][4];
    #pragma unroll
    for (int i = 0; i < 2; i++)
        #pragma unroll
        for (int j = 0; j < 8; j++)
            #pragma unroll
            for (int k = 0; k < 4; k++) acc[i][j][k] = 0.f;

    uint32_t aA = smem_u32(sA), aB = smem_u32(sB);
    uint32_t offA0 = (uint32_t)(((wm * 32 + (lane & 15)) * 40 + ((lane >> 4) << 3)) * 2);
    uint32_t offB0 = (uint32_t)(((lane & 15) * 136 + wn * 64 + ((lane >> 4) << 3)) * 2);

    for (int k0 = 0; k0 < KTOT; k0 += 32) {
        // ---- stage A chunk [128 x 32] fp16 (single plane)
        #pragma unroll
        for (int i = 0; i < 2; i++) {
            int lin = tid + 256 * i;             // 0..511
            int r = lin >> 2, c8 = lin & 3;      // 8 halves per slot
            int gr = row0 + r;
            uint4 v = make_uint4(0u, 0u, 0u, 0u);
            if (gr < NN) v = *(const uint4*)(A + (size_t)gr * LDA + k0 + c8 * 8);
            *(uint4*)((char*)sA + (r * 40 + c8 * 8) * 2) = v;
        }
        // ---- stage B chunk [32 x 128] from fp32 W -> fp16
        #pragma unroll
        for (int i = 0; i < 4; i++) {
            int lin = tid + 256 * i;
            int kr = lin >> 5, c4 = lin & 31;
            float4 v = *(const float4*)(W + (size_t)(k0 + kr) * ldw + ncol0 + c4 * 4);
            *(uint2*)((char*)sB + (kr * 136 + c4 * 4) * 2) = pack4h(v);
        }
        __syncthreads();
        #pragma unroll
        for (int kb = 0; kb < 32; kb += 16) {
            uint32_t a[2][4], bb[4][4];
            #pragma unroll
            for (int mi = 0; mi < 2; mi++)
                ldmx4(a[mi], aA + offA0 + (uint32_t)((mi * 16 * 40 + kb) * 2));
            #pragma unroll
            for (int g = 0; g < 4; g++)
                ldmx4t(bb[g], aB + offB0 + (uint32_t)((kb * 136 + g * 16) * 2));
            #pragma unroll
            for (int mi = 0; mi < 2; mi++)
                #pragma unroll
                for (int g = 0; g < 4; g++) {
                    mma16816h(acc[mi][2 * g],     a[mi], &bb[g][0]);
                    mma16816h(acc[mi][2 * g + 1], a[mi], &bb[g][2]);
                }
        }
        __syncthreads();
    }

    // ---- epilogue: half2 outputs
    int rbase = row0 + wm * 32 + (lane >> 2);
    #pragma unroll
    for (int mi = 0; mi < 2; mi++)
        #pragma unroll
        for (int h = 0; h < 2; h++) {
            int gr = rbase + mi * 16 + h * 8;
            if (gr >= NN) continue;
            float dd = H16 ? g_dis[gr] : 1.f;
            #pragma unroll
            for (int ni = 0; ni < 8; ni++) {
                int cl = wn * 64 + ni * 8 + (lane & 3) * 2;
                float v0 = acc[mi][ni][2 * h];
                float v1 = acc[mi][ni][2 * h + 1];
                if (HASB) { v0 += bias[cl]; v1 += bias[cl + 1]; }
                if (TANH) { v0 = tanhf(v0); v1 = tanhf(v1); }
                if (H16) {
                    ((__half2*)g_h16)[(size_t)gr * 64 + (cl >> 1)] =
                        __floats2half2_rn(dd * v0, dd * v1);
                } else {
                    *(__half2*)(C + (size_t)gr * LDC + cl) = __floats2half2_rn(v0, v1);
                }
            }
        }
}

__global__ void __launch_bounds__(256, 2) gemm_zc_mma(const float* __restrict__ Wz,
                                                      const float* __restrict__ bz,
                                                      const float* __restrict__ Wc,
                                                      const float* __restrict__ bc) {
    int conv = blockIdx.z;
    int nb = blockIdx.y * 128;
    const float* W = conv ? Wc : Wz;
    const float* b = conv ? bc : bz;
    gemm_mma<128, 256, 512, true, true, false>(
        (const __half*)g_xagg16 + conv * 128, W, 256, b + nb,
        (__half*)g_act16 + conv * 256 + nb, blockIdx.x * 128, nb);
}

__global__ void __launch_bounds__(256, 2) gemm_o_mma(const float* __restrict__ Wo) {
    gemm_mma<512, 512, 128, false, false, true>(
        (const __half*)g_act16, Wo, 128, nullptr, nullptr, blockIdx.x * 128, 0);
}

// ---------------- fused dtype detect + degree init ----------------
__global__ void detect_init_kernel(const unsigned int* __restrict__ w) {
    int i = blockIdx.x * blockDim.x + threadIdx.x;
    if (i < NN) g_deg[i] = 1;  // self loop pre-counted
    if (blockIdx.x == 0) {
        // If int64 (LE), high word of every value (<100000) is 0; sample 2048.
        int bad = 0;
        for (int k = threadIdx.x; k < 2048; k += blockDim.x)
            if (w[2 * k + 1] != 0u) bad = 1;
        if (__syncthreads_or(bad)) {
            if (threadIdx.x == 0) g_is64 = 0;
        } else {
            if (threadIdx.x == 0) g_is64 = 1;
        }
    }
}

// ---------------- degree / norm / CSR build ----------------
__global__ void count_kernel(const void* __restrict__ ei) {
    int e = blockIdx.x * blockDim.x + threadIdx.x;
    if (e >= EE) return;
    int d = g_is64 ? (int)((const long long*)ei)[EE + e] : ((const int*)ei)[EE + e];
    atomicAdd(&g_deg[d], 1);
}

__global__ void scan1_kernel() {
    __shared__ int sh[1024];
    int i = blockIdx.x * 1024 + threadIdx.x;
    int v = 0;
    if (i < NN) {
        int d = g_deg[i];
        g_dis[i] = rsqrtf((float)d);
        v = d - 1;
    }
    sh[threadIdx.x] = v;
    __syncthreads();
    for (int ofs = 1; ofs < 1024; ofs <<= 1) {
        int t = 0;
        if ((int)threadIdx.x >= ofs) t = sh[threadIdx.x - ofs];
        __syncthreads();
        sh[threadIdx.x] += t;
        __syncthreads();
    }
    int incl = sh[threadIdx.x];
    if (i < NN) g_off[i] = incl - v;
    if (threadIdx.x == 1023) g_bsum[blockIdx.x] = incl;
}

// parallel exclusive scan over the 98 block sums (1 block, 128 threads)
__global__ void scan2_kernel() {
    __shared__ int sh[128];
    int t = threadIdx.x;
    int v = (t < NB) ? g_bsum[t] : 0;
    sh[t] = v;
    __syncthreads();
    for (int ofs = 1; ofs < 128; ofs <<= 1) {
        int u = 0;
        if (t >= ofs) u = sh[t - ofs];
        __syncthreads();
        sh[t] += u;
        __syncthreads();
    }
    if (t < NB) g_bsum[t] = sh[t] - v;  // exclusive
}

__global__ void scan3_kernel() {
    int i = blockIdx.x * 1024 + threadIdx.x;
    if (i < NN) {
        int o = g_off[i] + g_bsum[blockIdx.x];
        g_off[i] = o;
        g_cur[i] = o;
    }
    if (i == 0) g_off[NN] = EE;
}

// ---------------- fused scatter (CSR fill) + cast (fp16 feature plane) -------
// Independent tasks after scan3/scan1 — run concurrently in one launch.
// blocks [0, SCAT_BLOCKS): scatter; blocks [SCAT_BLOCKS, +CAST_BLOCKS): cast.
__global__ void __launch_bounds__(256) scatter_cast_kernel(
        const void* __restrict__ ei,
        const float* __restrict__ lat, const float* __restrict__ cond) {
    int b = blockIdx.x;
    if (b < SCAT_BLOCKS) {
        int e = b * 256 + threadIdx.x;
        if (e >= EE) return;
        int s, d;
        if (g_is64) {
            const long long* p = (const long long*)ei;
            s = (int)p[e];
            d = (int)p[EE + e];
        } else {
            const int* p = (const int*)ei;
            s = p[e];
            d = p[EE + e];
        }
        int pos = atomicAdd(&g_cur[d], 1);
        g_srcs[pos] = s;
    } else {
        int t = (b - SCAT_BLOCKS) * 256 + threadIdx.x;  // over NN*128 half2 slots
        if (t >= NN * 128) return;
        int node = t >> 7;
        int c2 = t & 127;
        float dd = g_dis[node];
        float2 v;
        if (c2 < 64) v = ((const float2*)lat)[(size_t)node * 64 + c2];
        else         v = ((const float2*)cond)[(size_t)node * 64 + (c2 - 64)];
        ((__half2*)g_x16)[(size_t)t] = __floats2half2_rn(dd * v.x, dd * v.y);
    }
}

// ---------------- unpack-accumulate helpers ----------------
__device__ __forceinline__ void acc8(float* a, uint4 v) {
    const __half2* h = (const __half2*)&v;
    #pragma unroll
    for (int k = 0; k < 4; k++) {
        float2 f = __half22float2(h[k]);
        a[2 * k] += f.x;
        a[2 * k + 1] += f.y;
    }
}
__device__ __forceinline__ void acc4(float* a, uint2 v) {
    const __half2* h = (const __half2*)&v;
    float2 f0 = __half22float2(h[0]);
    float2 f1 = __half22float2(h[1]);
    a[0] += f0.x; a[1] += f0.y; a[2] += f1.x; a[3] += f1.y;
}

// ---------------- aggregation 1: fp16 gather, 512B/node, warp-per-node -----
__global__ void __launch_bounds__(256) aggx_kernel() {
    int gw = (int)((blockIdx.x * blockDim.x + threadIdx.x) >> 5);
    int lane = threadIdx.x & 31;
    if (gw >= NN) return;
    float dd = g_dis[gw];
    float a[8];
    #pragma unroll
    for (int k = 0; k < 8; k++) a[k] = 0.f;
    acc8(a, g_x16[(size_t)gw * 32 + lane]);  // self term (pre-scaled by dis)
    int beg = g_off[gw], end = g_off[gw + 1];
    #pragma unroll 4
    for (int j = beg; j < end; ++j) {
        int s = g_srcs[j];
        acc8(a, g_x16[(size_t)s * 32 + lane]);
    }
    uint4 o;
    __half2* oh = (__half2*)&o;
    #pragma unroll
    for (int k = 0; k < 4; k++)
        oh[k] = __floats2half2_rn(dd * a[2 * k], dd * a[2 * k + 1]);
    g_xagg16[(size_t)gw * 32 + lane] = o;
}

// ---------------- aggregation 2: fp16 gather, 256B/node, warp-per-node -----
__global__ void __launch_bounds__(256) agg2_kernel(const float* __restrict__ bo,
                                                   float* __restrict__ out) {
    int gw = (int)((blockIdx.x * blockDim.x + threadIdx.x) >> 5);
    int lane = threadIdx.x & 31;
    if (gw >= NN) return;
    float dd = g_dis[gw];
    float a[4];
    #pragma unroll
    for (int k = 0; k < 4; k++) a[k] = 0.f;
    acc4(a, g_h16[(size_t)gw * 32 + lane]);  // self term
    int beg = g_off[gw], end = g_off[gw + 1];
    #pragma unroll 4
    for (int j = beg; j < end; ++j) {
        int s = g_srcs[j];
        acc4(a, g_h16[(size_t)s * 32 + lane]);
    }
    float4 b = ((const float4*)bo)[lane];
    ((float4*)out)[(size_t)gw * 32 + lane] =
        make_float4(dd * a[0] + b.x, dd * a[1] + b.y, dd * a[2] + b.z, dd * a[3] + b.w);
}

// ---------------- launch ----------------
extern "C" void kernel_launch(void* const* d_in, const int* in_sizes, int n_in,
                              void* d_out, int out_size) {
    const float* latent    = (const float*)d_in[0];
    const float* condition = (const float*)d_in[1];
    const void*  ei        = d_in[2];
    const float* Wz = (const float*)d_in[3];
    const float* bz = (const float*)d_in[4];
    const float* Wc = (const float*)d_in[5];
    const float* bc = (const float*)d_in[6];
    const float* Wo = (const float*)d_in[7];
    const float* bo = (const float*)d_in[8];
    float* out = (float*)d_out;

    detect_init_kernel<<<(NN + 255) / 256, 256>>>((const unsigned int*)ei);
    count_kernel<<<(EE + 255) / 256, 256>>>(ei);
    scan1_kernel<<<NB, 1024>>>();
    scan2_kernel<<<1, 128>>>();
    scan3_kernel<<<NB, 1024>>>();
    scatter_cast_kernel<<<SCAT_BLOCKS + CAST_BLOCKS, 256>>>(ei, latent, condition);
    aggx_kernel<<<(NN * 32 + 255) / 256, 256>>>();

    int ntiles = (NN + 127) / 128;  // 782
    gemm_zc_mma<<<dim3(ntiles, 2, 2), 256>>>(Wz, bz, Wc, bc);
    gemm_o_mma<<<dim3(ntiles, 1, 1), 256>>>(Wo);

    agg2_kernel<<<(NN * 32 + 255) / 256, 256>>>(bo, out);
}